// round 1
// baseline (speedup 1.0000x reference)
#include <cuda_runtime.h>
#include <cuda_bf16.h>
#include <math.h>

// ---------------- constants ----------------
#define T        2048
#define HIDDEN   2048
#define NHEADS   32
#define NKV      8
#define HDIM     128
#define QSIZE    (NHEADS * HDIM)          // 4096
#define KVSIZE   (NKV * HDIM)             // 1024
#define QKVW     (QSIZE + 2 * KVSIZE)     // 6144
#define SCALING  0.08838834764831845f     // 1/sqrt(128)

// ---------------- scratch (no allocations allowed) ----------------
__device__ float g_qkv[T * QKVW];   // 50.3 MB
__device__ float g_o[T * QSIZE];    // 33.6 MB

// =====================================================================
// SGEMM: C[M,N] = A[M,K] * B[N,K]^T   (A,B,C row-major)
// 128x128 block, 8-deep K tile, 256 threads, 8x8 per-thread microtile.
// =====================================================================
__global__ __launch_bounds__(256) void sgemm_tn(
    const float* __restrict__ A, const float* __restrict__ B,
    float* __restrict__ C, int M, int N, int K)
{
    const int BM = 128, BN = 128, BK = 8;
    __shared__ float As[BK][BM];
    __shared__ float Bs[BK][BN];

    int tid = threadIdx.x;
    int m0 = blockIdx.y * BM;
    int n0 = blockIdx.x * BN;
    int tx = tid & 15;     // 0..15
    int ty = tid >> 4;     // 0..15

    float acc[8][8];
#pragma unroll
    for (int i = 0; i < 8; i++)
#pragma unroll
        for (int j = 0; j < 8; j++) acc[i][j] = 0.f;

    int lrow = tid >> 1;          // 0..127
    int lk   = (tid & 1) * 4;     // 0 or 4
    const float* Ap = A + (long)(m0 + lrow) * K + lk;
    const float* Bp = B + (long)(n0 + lrow) * K + lk;

    for (int k0 = 0; k0 < K; k0 += BK) {
        float4 av = *(const float4*)(Ap + k0);
        float4 bv = *(const float4*)(Bp + k0);
        As[lk + 0][lrow] = av.x; As[lk + 1][lrow] = av.y;
        As[lk + 2][lrow] = av.z; As[lk + 3][lrow] = av.w;
        Bs[lk + 0][lrow] = bv.x; Bs[lk + 1][lrow] = bv.y;
        Bs[lk + 2][lrow] = bv.z; Bs[lk + 3][lrow] = bv.w;
        __syncthreads();

#pragma unroll
        for (int kk = 0; kk < BK; kk++) {
            float a[8], b[8];
            *(float4*)(a)     = *(const float4*)&As[kk][ty * 8];
            *(float4*)(a + 4) = *(const float4*)&As[kk][ty * 8 + 4];
            *(float4*)(b)     = *(const float4*)&Bs[kk][tx * 8];
            *(float4*)(b + 4) = *(const float4*)&Bs[kk][tx * 8 + 4];
#pragma unroll
            for (int i = 0; i < 8; i++)
#pragma unroll
                for (int j = 0; j < 8; j++)
                    acc[i][j] = fmaf(a[i], b[j], acc[i][j]);
        }
        __syncthreads();
    }

#pragma unroll
    for (int i = 0; i < 8; i++) {
        int row = m0 + ty * 8 + i;
        float4 c0 = make_float4(acc[i][0], acc[i][1], acc[i][2], acc[i][3]);
        float4 c1 = make_float4(acc[i][4], acc[i][5], acc[i][6], acc[i][7]);
        *(float4*)&C[(long)row * N + n0 + tx * 8]     = c0;
        *(float4*)&C[(long)row * N + n0 + tx * 8 + 4] = c1;
    }
}

// =====================================================================
// Fused per-head RMSNorm + RoPE, in place on g_qkv.
// grid = (T, 40): heads 0..31 = q heads, 32..39 = k heads. 128 threads.
// =====================================================================
__global__ void rmsnorm_rope_kernel(
    float* __restrict__ qkv, const int* __restrict__ positions,
    const float* __restrict__ qw, const float* __restrict__ kw)
{
    int t  = blockIdx.x;
    int hh = blockIdx.y;
    int off = (hh < NHEADS) ? hh * HDIM : QSIZE + (hh - NHEADS) * HDIM;
    const float* w = (hh < NHEADS) ? qw : kw;
    float* x = qkv + (long)t * QKVW + off;

    int d = threadIdx.x;           // 0..127
    float v = x[d];
    float ss = v * v;
#pragma unroll
    for (int o = 16; o >= 1; o >>= 1)
        ss += __shfl_xor_sync(0xffffffffu, ss, o);

    __shared__ float sred[4];
    __shared__ float snorm;
    __shared__ float sx[HDIM];
    int lane = d & 31, wp = d >> 5;
    if (lane == 0) sred[wp] = ss;
    __syncthreads();
    if (d == 0) {
        float tot = sred[0] + sred[1] + sred[2] + sred[3];
        snorm = rsqrtf(tot / (float)HDIM + 1e-6f);
    }
    __syncthreads();

    float nv = v * snorm * w[d];
    sx[d] = nv;
    __syncthreads();

    if (d < 64) {
        float x1 = sx[d];
        float x2 = sx[d + 64];
        float pos = (float)positions[t];
        float invf = powf(10000.0f, -((float)d) / 64.0f);
        float ang = pos * invf;
        float c, s;
        sincosf(ang, &s, &c);
        x[d]      = x1 * c - x2 * s;
        x[d + 64] = x2 * c + x1 * s;
    }
}

// =====================================================================
// Flash attention (causal, GQA). One block = (64 q rows) x (1 head).
// 256 threads (16x16), online softmax, fp32.
// Dynamic smem: Qs[64][128] Ks[64][136] Vs[64][128] Ps[64][68]
// =====================================================================
#define BQ 64
#define BKV 64
#define KS_STRIDE 136
#define PS_STRIDE 68
#define FLASH_SMEM ((64*128 + 64*KS_STRIDE + 64*128 + 64*PS_STRIDE) * 4)

__global__ __launch_bounds__(256) void flash_kernel(
    const float* __restrict__ qkv, float* __restrict__ O)
{
    int qb = blockIdx.x;           // 0..31
    int h  = blockIdx.y;           // 0..31
    int kvh = h >> 2;              // group = 4
    int q0 = qb * BQ;

    extern __shared__ float sm[];
    float* Qs = sm;                              // [64][128]
    float* Ks = Qs + 64 * 128;                   // [64][136]
    float* Vs = Ks + 64 * KS_STRIDE;             // [64][128]
    float* Ps = Vs + 64 * 128;                   // [64][68]

    int tid = threadIdx.x;
    int tx = tid & 15;     // col group
    int ty = tid >> 4;     // row group

    // load Q tile
#pragma unroll
    for (int it = 0; it < 8; it++) {
        int v  = tid + it * 256;
        int s  = v >> 5;
        int dv = (v & 31) * 4;
        *(float4*)&Qs[s * 128 + dv] =
            *(const float4*)&qkv[(long)(q0 + s) * QKVW + h * HDIM + dv];
    }

    float m[4], l[4], o[4][8];
#pragma unroll
    for (int i = 0; i < 4; i++) {
        m[i] = -1e30f; l[i] = 0.f;
#pragma unroll
        for (int j = 0; j < 8; j++) o[i][j] = 0.f;
    }

    for (int kb = 0; kb <= qb; kb++) {
        // load K and V tiles
#pragma unroll
        for (int it = 0; it < 8; it++) {
            int v  = tid + it * 256;
            int s  = v >> 5;
            int dv = (v & 31) * 4;
            long base = (long)(kb * BKV + s) * QKVW;
            *(float4*)&Ks[s * KS_STRIDE + dv] =
                *(const float4*)&qkv[base + QSIZE + kvh * HDIM + dv];
            *(float4*)&Vs[s * 128 + dv] =
                *(const float4*)&qkv[base + QSIZE + KVSIZE + kvh * HDIM + dv];
        }
        __syncthreads();

        // S = Q K^T (scaled, masked)
        float sacc[4][4];
#pragma unroll
        for (int i = 0; i < 4; i++)
#pragma unroll
            for (int j = 0; j < 4; j++) sacc[i][j] = 0.f;

#pragma unroll 4
        for (int k = 0; k < HDIM; k += 4) {
            float4 a[4], b[4];
#pragma unroll
            for (int i = 0; i < 4; i++)
                a[i] = *(const float4*)&Qs[(ty * 4 + i) * 128 + k];
#pragma unroll
            for (int j = 0; j < 4; j++)
                b[j] = *(const float4*)&Ks[(tx * 4 + j) * KS_STRIDE + k];
#pragma unroll
            for (int i = 0; i < 4; i++)
#pragma unroll
                for (int j = 0; j < 4; j++) {
                    sacc[i][j] = fmaf(a[i].x, b[j].x, sacc[i][j]);
                    sacc[i][j] = fmaf(a[i].y, b[j].y, sacc[i][j]);
                    sacc[i][j] = fmaf(a[i].z, b[j].z, sacc[i][j]);
                    sacc[i][j] = fmaf(a[i].w, b[j].w, sacc[i][j]);
                }
        }

        // scale + causal mask + online softmax
#pragma unroll
        for (int i = 0; i < 4; i++) {
            int rs = q0 + ty * 4 + i;
            float mi = -1e30f;
#pragma unroll
            for (int j = 0; j < 4; j++) {
                int cs = kb * BKV + tx * 4 + j;
                float val = sacc[i][j] * SCALING;
                if (cs > rs) val = -1e30f;
                sacc[i][j] = val;
                mi = fmaxf(mi, val);
            }
#pragma unroll
            for (int off = 8; off >= 1; off >>= 1)
                mi = fmaxf(mi, __shfl_xor_sync(0xffffffffu, mi, off, 16));

            float mnew = fmaxf(m[i], mi);
            float corr = expf(m[i] - mnew);
            float lsum = 0.f;
#pragma unroll
            for (int j = 0; j < 4; j++) {
                float p = expf(sacc[i][j] - mnew);
                Ps[(ty * 4 + i) * PS_STRIDE + tx * 4 + j] = p;
                lsum += p;
            }
#pragma unroll
            for (int off = 8; off >= 1; off >>= 1)
                lsum += __shfl_xor_sync(0xffffffffu, lsum, off, 16);

            l[i] = l[i] * corr + lsum;
            m[i] = mnew;
#pragma unroll
            for (int j = 0; j < 8; j++) o[i][j] *= corr;
        }
        __syncthreads();

        // O += P V
#pragma unroll 4
        for (int s = 0; s < BKV; s++) {
            float p[4];
#pragma unroll
            for (int i = 0; i < 4; i++)
                p[i] = Ps[(ty * 4 + i) * PS_STRIDE + s];
            float4 v0 = *(const float4*)&Vs[s * 128 + tx * 8];
            float4 v1 = *(const float4*)&Vs[s * 128 + tx * 8 + 4];
#pragma unroll
            for (int i = 0; i < 4; i++) {
                o[i][0] = fmaf(p[i], v0.x, o[i][0]);
                o[i][1] = fmaf(p[i], v0.y, o[i][1]);
                o[i][2] = fmaf(p[i], v0.z, o[i][2]);
                o[i][3] = fmaf(p[i], v0.w, o[i][3]);
                o[i][4] = fmaf(p[i], v1.x, o[i][4]);
                o[i][5] = fmaf(p[i], v1.y, o[i][5]);
                o[i][6] = fmaf(p[i], v1.z, o[i][6]);
                o[i][7] = fmaf(p[i], v1.w, o[i][7]);
            }
        }
        __syncthreads();
    }

    // epilogue: O /= l, write out
#pragma unroll
    for (int i = 0; i < 4; i++) {
        float inv = 1.0f / l[i];
        int row = q0 + ty * 4 + i;
        float4 c0 = make_float4(o[i][0]*inv, o[i][1]*inv, o[i][2]*inv, o[i][3]*inv);
        float4 c1 = make_float4(o[i][4]*inv, o[i][5]*inv, o[i][6]*inv, o[i][7]*inv);
        long base = (long)row * QSIZE + h * HDIM + tx * 8;
        *(float4*)&O[base]     = c0;
        *(float4*)&O[base + 4] = c1;
    }
}

// =====================================================================
// launch
// =====================================================================
extern "C" void kernel_launch(void* const* d_in, const int* in_sizes, int n_in,
                              void* d_out, int out_size)
{
    const int*   positions = (const int*)d_in[0];
    const float* hidden    = (const float*)d_in[1];
    const float* wqkv      = (const float*)d_in[2];
    const float* wo        = (const float*)d_in[3];
    const float* qnw       = (const float*)d_in[4];
    const float* knw       = (const float*)d_in[5];
    float* out = (float*)d_out;

    float* qkv = nullptr;
    float* obuf = nullptr;
    cudaGetSymbolAddress((void**)&qkv, g_qkv);
    cudaGetSymbolAddress((void**)&obuf, g_o);

    cudaFuncSetAttribute(flash_kernel,
                         cudaFuncAttributeMaxDynamicSharedMemorySize,
                         FLASH_SMEM);

    // 1) qkv = hidden @ wqkv^T   [2048, 6144]
    {
        dim3 grid(QKVW / 128, T / 128);
        sgemm_tn<<<grid, 256>>>(hidden, wqkv, qkv, T, QKVW, HIDDEN);
    }
    // 2) per-head rmsnorm + rope (q and k heads) in place
    {
        dim3 grid(T, NHEADS + NKV);
        rmsnorm_rope_kernel<<<grid, 128>>>(qkv, positions, qnw, knw);
    }
    // 3) causal flash attention -> g_o [2048, 4096]
    {
        dim3 grid(T / BQ, NHEADS);
        flash_kernel<<<grid, 256, FLASH_SMEM>>>(qkv, obuf);
    }
    // 4) out = o @ wo^T   [2048, 2048]
    {
        dim3 grid(HIDDEN / 128, T / 128);
        sgemm_tn<<<grid, 256>>>(obuf, wo, out, T, HIDDEN, QSIZE);
    }
}

// round 2
// speedup vs baseline: 5.4208x; 5.4208x over previous
#include <cuda_runtime.h>
#include <cuda_bf16.h>
#include <math.h>

// ---------------- constants ----------------
#define T        2048
#define HIDDEN   2048
#define NHEADS   32
#define NKV      8
#define HDIM     128
#define QSIZE    (NHEADS * HDIM)          // 4096
#define KVSIZE   (NKV * HDIM)             // 1024
#define QKVW     (QSIZE + 2 * KVSIZE)     // 6144
#define SCALING  0.08838834764831845f     // 1/sqrt(128)

// ---------------- scratch (no allocations allowed) ----------------
__device__ float g_qkv[T * QKVW];   // 50.3 MB
__device__ float g_o[T * QSIZE];    // 33.6 MB

// ---------------- tf32 helpers ----------------
__device__ __forceinline__ unsigned f2tf(float x) {
    unsigned r;
    asm("cvt.rna.tf32.f32 %0, %1;" : "=r"(r) : "f"(x));
    return r;
}

// D += A * B  (m16n8k8, tf32 in, fp32 acc). acc updated in place.
__device__ __forceinline__ void mma_tf32(float c[4], const unsigned a[4], const unsigned b[2]) {
    asm("mma.sync.aligned.m16n8k8.row.col.f32.tf32.tf32.f32 "
        "{%0,%1,%2,%3},{%4,%5,%6,%7},{%8,%9},{%0,%1,%2,%3};"
        : "+f"(c[0]), "+f"(c[1]), "+f"(c[2]), "+f"(c[3])
        : "r"(a[0]), "r"(a[1]), "r"(a[2]), "r"(a[3]), "r"(b[0]), "r"(b[1]));
}

// =====================================================================
// tf32 tensor-core SGEMM: C[M,N] = A[M,K] * B[N,K]^T  (row-major)
// 128x128 block, BK=32, 256 threads = 8 warps (2 m x 4 n), warp 64x32.
// Double-buffered dynamic smem, stride 36 (bank-conflict-free frags).
// =====================================================================
#define GSTR 36
#define GSB  (128 * GSTR)
#define GEMM_SMEM (4 * GSB * 4)   // As[2]+Bs[2], 4B each = 73728 B

__global__ __launch_bounds__(256) void gemm_tf32(
    const float* __restrict__ A, const float* __restrict__ B,
    float* __restrict__ C, int M, int N, int K)
{
    extern __shared__ unsigned smg[];
    unsigned* As = smg;              // [2][128*36]
    unsigned* Bs = smg + 2 * GSB;    // [2][128*36]

    int tid = threadIdx.x;
    int lane = tid & 31, warp = tid >> 5;
    int gid = lane >> 2, tig = lane & 3;
    int wm = warp >> 2, wn = warp & 3;      // 2 x 4 warp grid
    int m0 = blockIdx.y * 128, n0 = blockIdx.x * 128;

    int lr = tid >> 3;          // 0..31
    int lc = (tid & 7) << 2;    // 0,4,...,28
    const float* Ag = A + (long)(m0 + lr) * K + lc;
    const float* Bg = B + (long)(n0 + lr) * K + lc;

    float acc[4][4][4];
#pragma unroll
    for (int mt = 0; mt < 4; mt++)
#pragma unroll
        for (int nt = 0; nt < 4; nt++)
#pragma unroll
            for (int r = 0; r < 4; r++) acc[mt][nt][r] = 0.f;

    float4 av[4], bv[4];

    // prologue: load tile 0
#pragma unroll
    for (int i = 0; i < 4; i++) {
        av[i] = *(const float4*)(Ag + (long)(i * 32) * K);
        bv[i] = *(const float4*)(Bg + (long)(i * 32) * K);
    }
#pragma unroll
    for (int i = 0; i < 4; i++) {
        *(uint4*)&As[(lr + i * 32) * GSTR + lc] =
            make_uint4(f2tf(av[i].x), f2tf(av[i].y), f2tf(av[i].z), f2tf(av[i].w));
        *(uint4*)&Bs[(lr + i * 32) * GSTR + lc] =
            make_uint4(f2tf(bv[i].x), f2tf(bv[i].y), f2tf(bv[i].z), f2tf(bv[i].w));
    }
    __syncthreads();

    int nk = K >> 5;
    for (int kt = 0; kt < nk; kt++) {
        int cur = kt & 1;
        if (kt + 1 < nk) {
            long koff = (long)(kt + 1) << 5;
#pragma unroll
            for (int i = 0; i < 4; i++) {
                av[i] = *(const float4*)(Ag + (long)(i * 32) * K + koff);
                bv[i] = *(const float4*)(Bg + (long)(i * 32) * K + koff);
            }
        }

        const unsigned* Ac = As + cur * GSB;
        const unsigned* Bc = Bs + cur * GSB;
#pragma unroll
        for (int kc = 0; kc < 4; kc++) {
            unsigned a[4][4], b[4][2];
#pragma unroll
            for (int mt = 0; mt < 4; mt++) {
                const unsigned* p = Ac + (wm * 64 + mt * 16 + gid) * GSTR + kc * 8 + tig;
                a[mt][0] = p[0];
                a[mt][1] = p[8 * GSTR];
                a[mt][2] = p[4];
                a[mt][3] = p[8 * GSTR + 4];
            }
#pragma unroll
            for (int nt = 0; nt < 4; nt++) {
                const unsigned* p = Bc + (wn * 32 + nt * 8 + gid) * GSTR + kc * 8 + tig;
                b[nt][0] = p[0];
                b[nt][1] = p[4];
            }
#pragma unroll
            for (int mt = 0; mt < 4; mt++)
#pragma unroll
                for (int nt = 0; nt < 4; nt++)
                    mma_tf32(acc[mt][nt], a[mt], b[nt]);
        }

        if (kt + 1 < nk) {
            int nxt = (kt & 1) ^ 1;
#pragma unroll
            for (int i = 0; i < 4; i++) {
                *(uint4*)&As[nxt * GSB + (lr + i * 32) * GSTR + lc] =
                    make_uint4(f2tf(av[i].x), f2tf(av[i].y), f2tf(av[i].z), f2tf(av[i].w));
                *(uint4*)&Bs[nxt * GSB + (lr + i * 32) * GSTR + lc] =
                    make_uint4(f2tf(bv[i].x), f2tf(bv[i].y), f2tf(bv[i].z), f2tf(bv[i].w));
            }
        }
        __syncthreads();
    }

    // epilogue
#pragma unroll
    for (int mt = 0; mt < 4; mt++) {
        int row = m0 + wm * 64 + mt * 16 + gid;
#pragma unroll
        for (int nt = 0; nt < 4; nt++) {
            int col = n0 + wn * 32 + nt * 8 + 2 * tig;
            *(float2*)&C[(long)row * N + col] = make_float2(acc[mt][nt][0], acc[mt][nt][1]);
            *(float2*)&C[(long)(row + 8) * N + col] = make_float2(acc[mt][nt][2], acc[mt][nt][3]);
        }
    }
}

// =====================================================================
// Fused per-head RMSNorm + RoPE, in place on g_qkv.
// grid = (T, 40): heads 0..31 = q heads, 32..39 = k heads. 128 threads.
// =====================================================================
__global__ void rmsnorm_rope_kernel(
    float* __restrict__ qkv, const int* __restrict__ positions,
    const float* __restrict__ qw, const float* __restrict__ kw)
{
    int t  = blockIdx.x;
    int hh = blockIdx.y;
    int off = (hh < NHEADS) ? hh * HDIM : QSIZE + (hh - NHEADS) * HDIM;
    const float* w = (hh < NHEADS) ? qw : kw;
    float* x = qkv + (long)t * QKVW + off;

    int d = threadIdx.x;           // 0..127
    float v = x[d];
    float ss = v * v;
#pragma unroll
    for (int o = 16; o >= 1; o >>= 1)
        ss += __shfl_xor_sync(0xffffffffu, ss, o);

    __shared__ float sred[4];
    __shared__ float snorm;
    __shared__ float sx[HDIM];
    int lane = d & 31, wp = d >> 5;
    if (lane == 0) sred[wp] = ss;
    __syncthreads();
    if (d == 0) {
        float tot = sred[0] + sred[1] + sred[2] + sred[3];
        snorm = rsqrtf(tot / (float)HDIM + 1e-6f);
    }
    __syncthreads();

    float nv = v * snorm * w[d];
    sx[d] = nv;
    __syncthreads();

    if (d < 64) {
        float x1 = sx[d];
        float x2 = sx[d + 64];
        float pos = (float)positions[t];
        float invf = powf(10000.0f, -((float)d) / 64.0f);
        float ang = pos * invf;
        float c, s;
        sincosf(ang, &s, &c);
        x[d]      = x1 * c - x2 * s;
        x[d + 64] = x2 * c + x1 * s;
    }
}

// =====================================================================
// Flash attention with tf32 tensor cores.
// Block: 128 q rows x 1 head. 8 warps, each owns 16 q rows.
// BKV=64. Online softmax in registers. Q pre-scaled by 1/sqrt(D).
// smem strides: Q/K=132, V=136, P=68 (all fragment LDS conflict-free).
// =====================================================================
#define FBQ 128
#define FBK 64
#define QSTRd 132
#define KSTRd 132
#define VSTRd 136
#define PSTRd 68
#define FLASH_SMEM ((FBQ*QSTRd + FBK*KSTRd + FBK*VSTRd + FBQ*PSTRd) * 4)  // 171008 B

__global__ __launch_bounds__(256) void flash_tf32(
    const float* __restrict__ qkv, float* __restrict__ O)
{
    int qb = blockIdx.x;           // 0..15
    int h  = blockIdx.y;           // 0..31
    int kvh = h >> 2;
    int q0 = qb * FBQ;

    extern __shared__ unsigned sm[];
    unsigned* Qs = sm;                       // [128][132] tf32
    unsigned* Ks = Qs + FBQ * QSTRd;         // [64][132]
    unsigned* Vs = Ks + FBK * KSTRd;         // [64][136]
    unsigned* Ps = Vs + FBK * VSTRd;         // [128][68]

    int tid = threadIdx.x;
    int warp = tid >> 5, lane = tid & 31;
    int gid = lane >> 2, tig = lane & 3;

    // load Q tile (scaled by 1/sqrt(D), converted to tf32)
#pragma unroll
    for (int i = 0; i < 16; i++) {
        int idx = tid + i * 256;               // 0..4095 float4s
        int r = idx >> 5;
        int c = (idx & 31) * 4;
        float4 v = *(const float4*)&qkv[(long)(q0 + r) * QKVW + h * HDIM + c];
        *(uint4*)&Qs[r * QSTRd + c] =
            make_uint4(f2tf(v.x * SCALING), f2tf(v.y * SCALING),
                       f2tf(v.z * SCALING), f2tf(v.w * SCALING));
    }

    float m0s = -1e30f, m1s = -1e30f, l0s = 0.f, l1s = 0.f;
    float oacc[16][4];
#pragma unroll
    for (int nt = 0; nt < 16; nt++)
#pragma unroll
        for (int r = 0; r < 4; r++) oacc[nt][r] = 0.f;

    int r0 = q0 + warp * 16 + gid;
    int r1 = r0 + 8;
    int kbmax = 2 * qb + 1;

    for (int kb = 0; kb <= kbmax; kb++) {
        __syncthreads();   // protect Ks/Vs (and make Q visible on iter 0)
        // load K, V tiles (64 rows x 128)
#pragma unroll
        for (int i = 0; i < 8; i++) {
            int idx = tid + i * 256;           // 0..2047 float4s
            int r = idx >> 5;
            int c = (idx & 31) * 4;
            long base = (long)(kb * FBK + r) * QKVW;
            float4 kv4 = *(const float4*)&qkv[base + QSIZE + kvh * HDIM + c];
            float4 vv4 = *(const float4*)&qkv[base + QSIZE + KVSIZE + kvh * HDIM + c];
            *(uint4*)&Ks[r * KSTRd + c] =
                make_uint4(f2tf(kv4.x), f2tf(kv4.y), f2tf(kv4.z), f2tf(kv4.w));
            *(uint4*)&Vs[r * VSTRd + c] =
                make_uint4(f2tf(vv4.x), f2tf(vv4.y), f2tf(vv4.z), f2tf(vv4.w));
        }
        __syncthreads();

        // ---- S = Q K^T (tensor cores) ----
        float sacc[8][4];
#pragma unroll
        for (int nt = 0; nt < 8; nt++)
#pragma unroll
            for (int r = 0; r < 4; r++) sacc[nt][r] = 0.f;

#pragma unroll
        for (int kc = 0; kc < 16; kc++) {
            unsigned a[4];
            const unsigned* qp = Qs + (warp * 16 + gid) * QSTRd + kc * 8 + tig;
            a[0] = qp[0];
            a[1] = qp[8 * QSTRd];
            a[2] = qp[4];
            a[3] = qp[8 * QSTRd + 4];
#pragma unroll
            for (int nt = 0; nt < 8; nt++) {
                unsigned b[2];
                const unsigned* kp = Ks + (nt * 8 + gid) * KSTRd + kc * 8 + tig;
                b[0] = kp[0];
                b[1] = kp[4];
                mma_tf32(sacc[nt], a, b);
            }
        }

        // ---- causal mask (only needed on last two blocks) ----
        if (kb >= 2 * qb) {
#pragma unroll
            for (int nt = 0; nt < 8; nt++) {
                int colb = kb * FBK + nt * 8 + 2 * tig;
                if (colb > r0)     sacc[nt][0] = -1e30f;
                if (colb + 1 > r0) sacc[nt][1] = -1e30f;
                if (colb > r1)     sacc[nt][2] = -1e30f;
                if (colb + 1 > r1) sacc[nt][3] = -1e30f;
            }
        }

        // ---- online softmax ----
        float mx0 = -1e30f, mx1 = -1e30f;
#pragma unroll
        for (int nt = 0; nt < 8; nt++) {
            mx0 = fmaxf(mx0, fmaxf(sacc[nt][0], sacc[nt][1]));
            mx1 = fmaxf(mx1, fmaxf(sacc[nt][2], sacc[nt][3]));
        }
        mx0 = fmaxf(mx0, __shfl_xor_sync(0xffffffffu, mx0, 1));
        mx0 = fmaxf(mx0, __shfl_xor_sync(0xffffffffu, mx0, 2));
        mx1 = fmaxf(mx1, __shfl_xor_sync(0xffffffffu, mx1, 1));
        mx1 = fmaxf(mx1, __shfl_xor_sync(0xffffffffu, mx1, 2));

        float mn0 = fmaxf(m0s, mx0);
        float mn1 = fmaxf(m1s, mx1);
        float corr0 = __expf(m0s - mn0);
        float corr1 = __expf(m1s - mn1);

        float ls0 = 0.f, ls1 = 0.f;
#pragma unroll
        for (int nt = 0; nt < 8; nt++) {
            sacc[nt][0] = __expf(sacc[nt][0] - mn0);
            sacc[nt][1] = __expf(sacc[nt][1] - mn0);
            sacc[nt][2] = __expf(sacc[nt][2] - mn1);
            sacc[nt][3] = __expf(sacc[nt][3] - mn1);
            ls0 += sacc[nt][0] + sacc[nt][1];
            ls1 += sacc[nt][2] + sacc[nt][3];
        }
        ls0 += __shfl_xor_sync(0xffffffffu, ls0, 1);
        ls0 += __shfl_xor_sync(0xffffffffu, ls0, 2);
        ls1 += __shfl_xor_sync(0xffffffffu, ls1, 1);
        ls1 += __shfl_xor_sync(0xffffffffu, ls1, 2);

        l0s = l0s * corr0 + ls0;
        l1s = l1s * corr1 + ls1;
        m0s = mn0;
        m1s = mn1;

        // scale running O
#pragma unroll
        for (int nt = 0; nt < 16; nt++) {
            oacc[nt][0] *= corr0;
            oacc[nt][1] *= corr0;
            oacc[nt][2] *= corr1;
            oacc[nt][3] *= corr1;
        }

        // write P (tf32) to smem — warp-private rows
        __syncwarp();
        {
            unsigned* pr0 = Ps + (warp * 16 + gid) * PSTRd + 2 * tig;
            unsigned* pr1 = pr0 + 8 * PSTRd;
#pragma unroll
            for (int nt = 0; nt < 8; nt++) {
                pr0[nt * 8]     = f2tf(sacc[nt][0]);
                pr0[nt * 8 + 1] = f2tf(sacc[nt][1]);
                pr1[nt * 8]     = f2tf(sacc[nt][2]);
                pr1[nt * 8 + 1] = f2tf(sacc[nt][3]);
            }
        }
        __syncwarp();

        // ---- O += P V (tensor cores) ----
#pragma unroll
        for (int kc = 0; kc < 8; kc++) {
            unsigned a[4];
            const unsigned* pp = Ps + (warp * 16 + gid) * PSTRd + kc * 8 + tig;
            a[0] = pp[0];
            a[1] = pp[8 * PSTRd];
            a[2] = pp[4];
            a[3] = pp[8 * PSTRd + 4];
#pragma unroll
            for (int nt = 0; nt < 16; nt++) {
                unsigned b[2];
                const unsigned* vp = Vs + (kc * 8 + tig) * VSTRd + nt * 8 + gid;
                b[0] = vp[0];
                b[1] = vp[4 * VSTRd];
                mma_tf32(oacc[nt], a, b);
            }
        }
    }

    // epilogue: normalize and write out
    float inv0 = 1.0f / l0s;
    float inv1 = 1.0f / l1s;
#pragma unroll
    for (int nt = 0; nt < 16; nt++) {
        int col = h * HDIM + nt * 8 + 2 * tig;
        *(float2*)&O[(long)r0 * QSIZE + col] =
            make_float2(oacc[nt][0] * inv0, oacc[nt][1] * inv0);
        *(float2*)&O[(long)r1 * QSIZE + col] =
            make_float2(oacc[nt][2] * inv1, oacc[nt][3] * inv1);
    }
}

// =====================================================================
// launch
// =====================================================================
extern "C" void kernel_launch(void* const* d_in, const int* in_sizes, int n_in,
                              void* d_out, int out_size)
{
    const int*   positions = (const int*)d_in[0];
    const float* hidden    = (const float*)d_in[1];
    const float* wqkv      = (const float*)d_in[2];
    const float* wo        = (const float*)d_in[3];
    const float* qnw       = (const float*)d_in[4];
    const float* knw       = (const float*)d_in[5];
    float* out = (float*)d_out;

    float* qkv = nullptr;
    float* obuf = nullptr;
    cudaGetSymbolAddress((void**)&qkv, g_qkv);
    cudaGetSymbolAddress((void**)&obuf, g_o);

    static bool attr_done = false;
    if (!attr_done) {
        cudaFuncSetAttribute(gemm_tf32,
                             cudaFuncAttributeMaxDynamicSharedMemorySize, GEMM_SMEM);
        cudaFuncSetAttribute(flash_tf32,
                             cudaFuncAttributeMaxDynamicSharedMemorySize, FLASH_SMEM);
        attr_done = true;
    }

    // 1) qkv = hidden @ wqkv^T   [2048, 6144]
    {
        dim3 grid(QKVW / 128, T / 128);
        gemm_tf32<<<grid, 256, GEMM_SMEM>>>(hidden, wqkv, qkv, T, QKVW, HIDDEN);
    }
    // 2) per-head rmsnorm + rope (q and k heads) in place
    {
        dim3 grid(T, NHEADS + NKV);
        rmsnorm_rope_kernel<<<grid, 128>>>(qkv, positions, qnw, knw);
    }
    // 3) causal flash attention -> g_o [2048, 4096]
    {
        dim3 grid(T / FBQ, NHEADS);
        flash_tf32<<<grid, 256, FLASH_SMEM>>>(qkv, obuf);
    }
    // 4) out = o @ wo^T   [2048, 2048]
    {
        dim3 grid(HIDDEN / 128, T / 128);
        gemm_tf32<<<grid, 256, GEMM_SMEM>>>(obuf, wo, out, T, HIDDEN, QSIZE);
    }
}

// round 3
// speedup vs baseline: 6.9108x; 1.2749x over previous
#include <cuda_runtime.h>
#include <cuda_fp16.h>
#include <math.h>

// ---------------- constants ----------------
#define T        2048
#define HIDDEN   2048
#define NHEADS   32
#define NKV      8
#define HDIM     128
#define QSIZE    (NHEADS * HDIM)          // 4096
#define KVSIZE   (NKV * HDIM)             // 1024
#define QKVW     (QSIZE + 2 * KVSIZE)     // 6144
#define SCALING  0.08838834764831845f     // 1/sqrt(128)

// ---------------- scratch (no allocations allowed) ----------------
__device__ float  g_qkv[T * QKVW];            // fp32 qkv
__device__ float  g_o[T * QSIZE];             // fp32 attention out
__device__ __half g_q16[NHEADS * T * HDIM];   // head-major, scaled
__device__ __half g_k16[NKV * T * HDIM];      // head-major
__device__ __half g_v16[NKV * T * HDIM];      // head-major

// ---------------- ptx helpers ----------------
__device__ __forceinline__ unsigned smem_u32(const void* p) {
    return (unsigned)__cvta_generic_to_shared(p);
}
__device__ __forceinline__ void ldsm4(unsigned r[4], unsigned addr) {
    asm volatile("ldmatrix.sync.aligned.m8n8.x4.shared.b16 {%0,%1,%2,%3},[%4];"
                 : "=r"(r[0]), "=r"(r[1]), "=r"(r[2]), "=r"(r[3]) : "r"(addr));
}
__device__ __forceinline__ void ldsm4t(unsigned r[4], unsigned addr) {
    asm volatile("ldmatrix.sync.aligned.m8n8.x4.trans.shared.b16 {%0,%1,%2,%3},[%4];"
                 : "=r"(r[0]), "=r"(r[1]), "=r"(r[2]), "=r"(r[3]) : "r"(addr));
}
__device__ __forceinline__ void mma_f16(float c[4], const unsigned a[4],
                                        unsigned b0, unsigned b1) {
    asm volatile("mma.sync.aligned.m16n8k16.row.col.f32.f16.f16.f32 "
                 "{%0,%1,%2,%3},{%4,%5,%6,%7},{%8,%9},{%0,%1,%2,%3};"
                 : "+f"(c[0]), "+f"(c[1]), "+f"(c[2]), "+f"(c[3])
                 : "r"(a[0]), "r"(a[1]), "r"(a[2]), "r"(a[3]), "r"(b0), "r"(b1));
}
__device__ __forceinline__ void cp16(unsigned saddr, const void* g) {
    asm volatile("cp.async.cg.shared.global [%0],[%1],16;" :: "r"(saddr), "l"(g));
}
__device__ __forceinline__ void cp_commit() {
    asm volatile("cp.async.commit_group;");
}
__device__ __forceinline__ void cp_wait_all() {
    asm volatile("cp.async.wait_group 0;");
}
__device__ __forceinline__ unsigned pack_h2(float a, float b) {
    __half2 h = __floats2half2_rn(a, b);
    return *reinterpret_cast<unsigned*>(&h);
}

// =====================================================================
// fp16 tensor-core GEMM: C[M,N](f32) = A[M,K](f32->h) * B[N,K](f32->h)^T
// 128x128 block, BK=32, 256 threads = 8 warps (2m x 4n), warp 64x32.
// smem stride 72 halves (144B): conflict-free for LDSM, 16B aligned.
// =====================================================================
#define GSTRH 72
#define GTILE (128 * GSTRH)                 // halves per stage per matrix
#define GEMM_SMEM (4 * GTILE * 2)           // 73728 B

__global__ __launch_bounds__(256, 2) void gemm_h16(
    const float* __restrict__ A, const float* __restrict__ B,
    float* __restrict__ C, int M, int N, int K)
{
    extern __shared__ __half smh[];
    __half* As = smh;                 // [2][GTILE]
    __half* Bs = smh + 2 * GTILE;     // [2][GTILE]

    int tid = threadIdx.x;
    int lane = tid & 31, warp = tid >> 5;
    int gid = lane >> 2, tig = lane & 3;
    int wm = warp >> 2, wn = warp & 3;
    int m0 = blockIdx.y * 128, n0 = blockIdx.x * 128;

    // global load mapping: each thread loads 16 consecutive floats (2 chunks)
    int lrow = tid >> 1;            // 0..127
    int lch  = (tid & 1) * 2;       // chunk 0 or 2 (8 halves per chunk)
    const float* Ag = A + (long)(m0 + lrow) * K + lch * 8;
    const float* Bg = B + (long)(n0 + lrow) * K + lch * 8;
    __half* Asw = As + lrow * GSTRH + lch * 8;
    __half* Bsw = Bs + lrow * GSTRH + lch * 8;

    float acc[4][4][4];
#pragma unroll
    for (int mt = 0; mt < 4; mt++)
#pragma unroll
        for (int nt = 0; nt < 4; nt++)
#pragma unroll
            for (int r = 0; r < 4; r++) acc[mt][nt][r] = 0.f;

    float4 av[4], bv[4];
    // prologue: load tile 0
#pragma unroll
    for (int j = 0; j < 4; j++) {
        av[j] = *(const float4*)(Ag + j * 4);
        bv[j] = *(const float4*)(Bg + j * 4);
    }
#pragma unroll
    for (int p = 0; p < 2; p++) {
        uint4 ha = make_uint4(pack_h2(av[2*p].x, av[2*p].y), pack_h2(av[2*p].z, av[2*p].w),
                              pack_h2(av[2*p+1].x, av[2*p+1].y), pack_h2(av[2*p+1].z, av[2*p+1].w));
        uint4 hb = make_uint4(pack_h2(bv[2*p].x, bv[2*p].y), pack_h2(bv[2*p].z, bv[2*p].w),
                              pack_h2(bv[2*p+1].x, bv[2*p+1].y), pack_h2(bv[2*p+1].z, bv[2*p+1].w));
        *(uint4*)(Asw + p * 8) = ha;
        *(uint4*)(Bsw + p * 8) = hb;
    }
    __syncthreads();

    int nk = K >> 5;
    for (int kt = 0; kt < nk; kt++) {
        int cur = kt & 1;
        if (kt + 1 < nk) {
            long koff = (long)(kt + 1) << 5;
#pragma unroll
            for (int j = 0; j < 4; j++) {
                av[j] = *(const float4*)(Ag + koff + j * 4);
                bv[j] = *(const float4*)(Bg + koff + j * 4);
            }
        }

        const __half* Ac = As + cur * GTILE;
        const __half* Bc = Bs + cur * GTILE;
#pragma unroll
        for (int kc = 0; kc < 2; kc++) {
            unsigned aq[4][4], bk[2][4];
#pragma unroll
            for (int mt = 0; mt < 4; mt++) {
                int row = wm * 64 + mt * 16 + (lane & 15);
                int ch  = kc * 2 + (lane >> 4);
                ldsm4(aq[mt], smem_u32(Ac + row * GSTRH + ch * 8));
            }
#pragma unroll
            for (int ntp = 0; ntp < 2; ntp++) {
                int row = wn * 32 + ntp * 16 + (lane & 7) + ((lane >> 4) << 3);
                int ch  = kc * 2 + ((lane >> 3) & 1);
                ldsm4(bk[ntp], smem_u32(Bc + row * GSTRH + ch * 8));
            }
#pragma unroll
            for (int mt = 0; mt < 4; mt++)
#pragma unroll
                for (int ntp = 0; ntp < 2; ntp++) {
                    mma_f16(acc[mt][2*ntp],   aq[mt], bk[ntp][0], bk[ntp][1]);
                    mma_f16(acc[mt][2*ntp+1], aq[mt], bk[ntp][2], bk[ntp][3]);
                }
        }

        if (kt + 1 < nk) {
            __half* Asn = As + ((cur ^ 1) * GTILE) + lrow * GSTRH + lch * 8;
            __half* Bsn = Bs + ((cur ^ 1) * GTILE) + lrow * GSTRH + lch * 8;
#pragma unroll
            for (int p = 0; p < 2; p++) {
                uint4 ha = make_uint4(pack_h2(av[2*p].x, av[2*p].y), pack_h2(av[2*p].z, av[2*p].w),
                                      pack_h2(av[2*p+1].x, av[2*p+1].y), pack_h2(av[2*p+1].z, av[2*p+1].w));
                uint4 hb = make_uint4(pack_h2(bv[2*p].x, bv[2*p].y), pack_h2(bv[2*p].z, bv[2*p].w),
                                      pack_h2(bv[2*p+1].x, bv[2*p+1].y), pack_h2(bv[2*p+1].z, bv[2*p+1].w));
                *(uint4*)(Asn + p * 8) = ha;
                *(uint4*)(Bsn + p * 8) = hb;
            }
        }
        __syncthreads();
    }

    // epilogue
#pragma unroll
    for (int mt = 0; mt < 4; mt++) {
        int row = m0 + wm * 64 + mt * 16 + gid;
#pragma unroll
        for (int nt = 0; nt < 4; nt++) {
            int col = n0 + wn * 32 + nt * 8 + 2 * tig;
            *(float2*)&C[(long)row * N + col] = make_float2(acc[mt][nt][0], acc[mt][nt][1]);
            *(float2*)&C[(long)(row + 8) * N + col] = make_float2(acc[mt][nt][2], acc[mt][nt][3]);
        }
    }
}

// =====================================================================
// Fused per-head RMSNorm + RoPE + fp16 conversion into head-major bufs.
// grid = (T, 48): 0..31 q heads, 32..39 k heads, 40..47 v heads.
// q written pre-scaled by 1/sqrt(D).
// =====================================================================
__global__ void rmsnorm_rope_kernel(
    const float* __restrict__ qkv, const int* __restrict__ positions,
    const float* __restrict__ qw, const float* __restrict__ kw,
    __half* __restrict__ q16, __half* __restrict__ k16, __half* __restrict__ v16)
{
    int t  = blockIdx.x;
    int hh = blockIdx.y;
    int d  = threadIdx.x;          // 0..127

    if (hh >= NHEADS + NKV) {      // v head: plain convert
        int vh = hh - NHEADS - NKV;
        float v = qkv[(long)t * QKVW + QSIZE + KVSIZE + vh * HDIM + d];
        v16[((long)vh * T + t) * HDIM + d] = __float2half_rn(v);
        return;
    }

    bool isq = (hh < NHEADS);
    int off = isq ? hh * HDIM : QSIZE + (hh - NHEADS) * HDIM;
    const float* w = isq ? qw : kw;
    const float* x = qkv + (long)t * QKVW + off;
    __half* outp = isq ? (q16 + ((long)hh * T + t) * HDIM)
                       : (k16 + ((long)(hh - NHEADS) * T + t) * HDIM);
    float oscale = isq ? SCALING : 1.0f;

    float v = x[d];
    float ss = v * v;
#pragma unroll
    for (int o = 16; o >= 1; o >>= 1)
        ss += __shfl_xor_sync(0xffffffffu, ss, o);

    __shared__ float sred[4];
    __shared__ float snorm;
    __shared__ float sx[HDIM];
    int lane = d & 31, wp = d >> 5;
    if (lane == 0) sred[wp] = ss;
    __syncthreads();
    if (d == 0) {
        float tot = sred[0] + sred[1] + sred[2] + sred[3];
        snorm = rsqrtf(tot / (float)HDIM + 1e-6f);
    }
    __syncthreads();

    float nv = v * snorm * w[d];
    sx[d] = nv;
    __syncthreads();

    if (d < 64) {
        float x1 = sx[d];
        float x2 = sx[d + 64];
        float pos = (float)positions[t];
        float invf = powf(10000.0f, -((float)d) / 64.0f);
        float ang = pos * invf;
        float c, s;
        sincosf(ang, &s, &c);
        outp[d]      = __float2half_rn((x1 * c - x2 * s) * oscale);
        outp[d + 64] = __float2half_rn((x2 * c + x1 * s) * oscale);
    }
}

// =====================================================================
// fp16 flash attention (causal, GQA).
// Block: 128 q rows x 1 head, 8 warps (16 rows each). BKV=64.
// KV double-buffered via cp.async. P stays in registers.
// smem stride 136 halves (272B): conflict-free LDSM, 16B aligned.
// =====================================================================
#define FSTR 136
#define FQ_H (128 * FSTR)
#define FKV_H (64 * FSTR)
#define FLASH_SMEM ((FQ_H + 4 * FKV_H) * 2)   // 104448 B

__global__ __launch_bounds__(256, 2) void flash_h16(
    const __half* __restrict__ Q, const __half* __restrict__ Kh,
    const __half* __restrict__ Vh, float* __restrict__ O)
{
    int qb = blockIdx.x;
    int h  = blockIdx.y;
    int kvh = h >> 2;
    int q0 = qb * 128;

    extern __shared__ __half smf[];
    __half* Qs = smf;                 // [128][136]
    __half* Ks = smf + FQ_H;          // [2][64][136]
    __half* Vs = Ks + 2 * FKV_H;      // [2][64][136]

    int tid = threadIdx.x;
    int lane = tid & 31, warp = tid >> 5;
    int gid = lane >> 2, tig = lane & 3;

    const __half* Qg = Q + ((long)h * T + q0) * HDIM;
    const __half* Kg = Kh + (long)kvh * T * HDIM;
    const __half* Vg = Vh + (long)kvh * T * HDIM;

    // prologue: Q tile (128 rows x 16 chunks), 8 chunks per thread
#pragma unroll
    for (int i = 0; i < 8; i++) {
        int idx = tid + i * 256;
        int r = idx >> 4, c = idx & 15;
        cp16(smem_u32(Qs + r * FSTR + c * 8), Qg + r * HDIM + c * 8);
    }
    // KV block 0
#pragma unroll
    for (int i = 0; i < 4; i++) {
        int idx = tid + i * 256;
        int r = idx >> 4, c = idx & 15;
        cp16(smem_u32(Ks + r * FSTR + c * 8), Kg + (long)r * HDIM + c * 8);
        cp16(smem_u32(Vs + r * FSTR + c * 8), Vg + (long)r * HDIM + c * 8);
    }
    cp_commit();

    float m0s = -1e30f, m1s = -1e30f, l0s = 0.f, l1s = 0.f;
    float oacc[16][4];
#pragma unroll
    for (int nt = 0; nt < 16; nt++)
#pragma unroll
        for (int r = 0; r < 4; r++) oacc[nt][r] = 0.f;

    int r0 = q0 + warp * 16 + gid;
    int r1 = r0 + 8;
    int kbmax = 2 * qb + 1;

    for (int kb = 0; kb <= kbmax; kb++) {
        cp_wait_all();
        __syncthreads();

        // prefetch next KV block into the other buffer
        if (kb < kbmax) {
            __half* Kn = Ks + ((kb + 1) & 1) * FKV_H;
            __half* Vn = Vs + ((kb + 1) & 1) * FKV_H;
            long rowoff = (long)(kb + 1) * 64;
#pragma unroll
            for (int i = 0; i < 4; i++) {
                int idx = tid + i * 256;
                int r = idx >> 4, c = idx & 15;
                cp16(smem_u32(Kn + r * FSTR + c * 8), Kg + (rowoff + r) * HDIM + c * 8);
                cp16(smem_u32(Vn + r * FSTR + c * 8), Vg + (rowoff + r) * HDIM + c * 8);
            }
        }
        cp_commit();

        const __half* Kc = Ks + (kb & 1) * FKV_H;
        const __half* Vc = Vs + (kb & 1) * FKV_H;

        // ---- S = Q K^T ----
        float sacc[8][4];
#pragma unroll
        for (int nt = 0; nt < 8; nt++)
#pragma unroll
            for (int r = 0; r < 4; r++) sacc[nt][r] = 0.f;

#pragma unroll
        for (int kc = 0; kc < 8; kc++) {
            unsigned aq[4];
            {
                int row = warp * 16 + (lane & 15);
                int ch  = kc * 2 + (lane >> 4);
                ldsm4(aq, smem_u32(Qs + row * FSTR + ch * 8));
            }
#pragma unroll
            for (int ntp = 0; ntp < 4; ntp++) {
                unsigned bk[4];
                int row = ntp * 16 + (lane & 7) + ((lane >> 4) << 3);
                int ch  = kc * 2 + ((lane >> 3) & 1);
                ldsm4(bk, smem_u32(Kc + row * FSTR + ch * 8));
                mma_f16(sacc[2*ntp],   aq, bk[0], bk[1]);
                mma_f16(sacc[2*ntp+1], aq, bk[2], bk[3]);
            }
        }

        // ---- causal mask (last two kv blocks only) ----
        if (kb >= 2 * qb) {
#pragma unroll
            for (int nt = 0; nt < 8; nt++) {
                int colb = kb * 64 + nt * 8 + 2 * tig;
                if (colb > r0)     sacc[nt][0] = -1e30f;
                if (colb + 1 > r0) sacc[nt][1] = -1e30f;
                if (colb > r1)     sacc[nt][2] = -1e30f;
                if (colb + 1 > r1) sacc[nt][3] = -1e30f;
            }
        }

        // ---- online softmax ----
        float mx0 = -1e30f, mx1 = -1e30f;
#pragma unroll
        for (int nt = 0; nt < 8; nt++) {
            mx0 = fmaxf(mx0, fmaxf(sacc[nt][0], sacc[nt][1]));
            mx1 = fmaxf(mx1, fmaxf(sacc[nt][2], sacc[nt][3]));
        }
        mx0 = fmaxf(mx0, __shfl_xor_sync(0xffffffffu, mx0, 1));
        mx0 = fmaxf(mx0, __shfl_xor_sync(0xffffffffu, mx0, 2));
        mx1 = fmaxf(mx1, __shfl_xor_sync(0xffffffffu, mx1, 1));
        mx1 = fmaxf(mx1, __shfl_xor_sync(0xffffffffu, mx1, 2));

        float mn0 = fmaxf(m0s, mx0);
        float mn1 = fmaxf(m1s, mx1);
        float corr0 = __expf(m0s - mn0);
        float corr1 = __expf(m1s - mn1);

        float ls0 = 0.f, ls1 = 0.f;
#pragma unroll
        for (int nt = 0; nt < 8; nt++) {
            sacc[nt][0] = __expf(sacc[nt][0] - mn0);
            sacc[nt][1] = __expf(sacc[nt][1] - mn0);
            sacc[nt][2] = __expf(sacc[nt][2] - mn1);
            sacc[nt][3] = __expf(sacc[nt][3] - mn1);
            ls0 += sacc[nt][0] + sacc[nt][1];
            ls1 += sacc[nt][2] + sacc[nt][3];
        }
        ls0 += __shfl_xor_sync(0xffffffffu, ls0, 1);
        ls0 += __shfl_xor_sync(0xffffffffu, ls0, 2);
        ls1 += __shfl_xor_sync(0xffffffffu, ls1, 1);
        ls1 += __shfl_xor_sync(0xffffffffu, ls1, 2);

        l0s = l0s * corr0 + ls0;
        l1s = l1s * corr1 + ls1;
        m0s = mn0;
        m1s = mn1;

#pragma unroll
        for (int nt = 0; nt < 16; nt++) {
            oacc[nt][0] *= corr0;
            oacc[nt][1] *= corr0;
            oacc[nt][2] *= corr1;
            oacc[nt][3] *= corr1;
        }

        // ---- O += P V (P from registers) ----
#pragma unroll
        for (int kc2 = 0; kc2 < 4; kc2++) {
            unsigned ap[4];
            ap[0] = pack_h2(sacc[2*kc2][0],   sacc[2*kc2][1]);
            ap[1] = pack_h2(sacc[2*kc2][2],   sacc[2*kc2][3]);
            ap[2] = pack_h2(sacc[2*kc2+1][0], sacc[2*kc2+1][1]);
            ap[3] = pack_h2(sacc[2*kc2+1][2], sacc[2*kc2+1][3]);
#pragma unroll
            for (int ntp = 0; ntp < 8; ntp++) {
                unsigned bv[4];
                int row = kc2 * 16 + (lane & 7) + (((lane >> 3) & 1) << 3);
                int ch  = ntp * 2 + (lane >> 4);
                ldsm4t(bv, smem_u32(Vc + row * FSTR + ch * 8));
                mma_f16(oacc[2*ntp],   ap, bv[0], bv[1]);
                mma_f16(oacc[2*ntp+1], ap, bv[2], bv[3]);
            }
        }
    }

    // epilogue
    float inv0 = 1.0f / l0s;
    float inv1 = 1.0f / l1s;
#pragma unroll
    for (int nt = 0; nt < 16; nt++) {
        int col = h * HDIM + nt * 8 + 2 * tig;
        *(float2*)&O[(long)r0 * QSIZE + col] =
            make_float2(oacc[nt][0] * inv0, oacc[nt][1] * inv0);
        *(float2*)&O[(long)r1 * QSIZE + col] =
            make_float2(oacc[nt][2] * inv1, oacc[nt][3] * inv1);
    }
}

// =====================================================================
// launch
// =====================================================================
extern "C" void kernel_launch(void* const* d_in, const int* in_sizes, int n_in,
                              void* d_out, int out_size)
{
    const int*   positions = (const int*)d_in[0];
    const float* hidden    = (const float*)d_in[1];
    const float* wqkv      = (const float*)d_in[2];
    const float* wo        = (const float*)d_in[3];
    const float* qnw       = (const float*)d_in[4];
    const float* knw       = (const float*)d_in[5];
    float* out = (float*)d_out;

    float *qkv = nullptr, *obuf = nullptr;
    __half *q16 = nullptr, *k16 = nullptr, *v16 = nullptr;
    cudaGetSymbolAddress((void**)&qkv, g_qkv);
    cudaGetSymbolAddress((void**)&obuf, g_o);
    cudaGetSymbolAddress((void**)&q16, g_q16);
    cudaGetSymbolAddress((void**)&k16, g_k16);
    cudaGetSymbolAddress((void**)&v16, g_v16);

    static bool attr_done = false;
    if (!attr_done) {
        cudaFuncSetAttribute(gemm_h16,
                             cudaFuncAttributeMaxDynamicSharedMemorySize, GEMM_SMEM);
        cudaFuncSetAttribute(flash_h16,
                             cudaFuncAttributeMaxDynamicSharedMemorySize, FLASH_SMEM);
        attr_done = true;
    }

    // 1) qkv = hidden @ wqkv^T   [2048, 6144]
    {
        dim3 grid(QKVW / 128, T / 128);
        gemm_h16<<<grid, 256, GEMM_SMEM>>>(hidden, wqkv, qkv, T, QKVW, HIDDEN);
    }
    // 2) rmsnorm + rope + fp16 head-major repack (q scaled)
    {
        dim3 grid(T, NHEADS + 2 * NKV);
        rmsnorm_rope_kernel<<<grid, 128>>>(qkv, positions, qnw, knw, q16, k16, v16);
    }
    // 3) causal flash attention -> g_o [2048, 4096] fp32
    {
        dim3 grid(T / 128, NHEADS);
        flash_h16<<<grid, 256, FLASH_SMEM>>>(q16, k16, v16, obuf);
    }
    // 4) out = o @ wo^T   [2048, 2048]
    {
        dim3 grid(HIDDEN / 128, T / 128);
        gemm_h16<<<grid, 256, GEMM_SMEM>>>(obuf, wo, out, T, HIDDEN, QSIZE);
    }
}

// round 4
// speedup vs baseline: 10.4947x; 1.5186x over previous
#include <cuda_runtime.h>
#include <cuda_fp16.h>
#include <math.h>

// ---------------- constants ----------------
#define T        2048
#define HIDDEN   2048
#define NHEADS   32
#define NKV      8
#define HDIM     128
#define QSIZE    (NHEADS * HDIM)          // 4096
#define KVSIZE   (NKV * HDIM)             // 1024
#define QKVW     (QSIZE + 2 * KVSIZE)     // 6144
#define SCALING  0.08838834764831845f     // 1/sqrt(128)

// ---------------- scratch (no allocations allowed) ----------------
__device__ float  g_qkv[T * QKVW];             // fp32 qkv (gemm out, norm in)
__device__ __half g_h16[T * HIDDEN];           // hidden fp16
__device__ __half g_wqkv16[QKVW * HIDDEN];     // wqkv fp16
__device__ __half g_wo16[HIDDEN * QSIZE];      // wo fp16
__device__ __half g_q16[NHEADS * T * HDIM];    // head-major, scaled
__device__ __half g_k16[NKV * T * HDIM];       // head-major
__device__ __half g_v16[NKV * T * HDIM];       // head-major
__device__ __half g_o16[T * QSIZE];            // attention out fp16

// ---------------- ptx helpers ----------------
__device__ __forceinline__ unsigned smem_u32(const void* p) {
    return (unsigned)__cvta_generic_to_shared(p);
}
__device__ __forceinline__ void ldsm4(unsigned r[4], unsigned addr) {
    asm volatile("ldmatrix.sync.aligned.m8n8.x4.shared.b16 {%0,%1,%2,%3},[%4];"
                 : "=r"(r[0]), "=r"(r[1]), "=r"(r[2]), "=r"(r[3]) : "r"(addr));
}
__device__ __forceinline__ void ldsm4t(unsigned r[4], unsigned addr) {
    asm volatile("ldmatrix.sync.aligned.m8n8.x4.trans.shared.b16 {%0,%1,%2,%3},[%4];"
                 : "=r"(r[0]), "=r"(r[1]), "=r"(r[2]), "=r"(r[3]) : "r"(addr));
}
__device__ __forceinline__ void mma_f16(float c[4], const unsigned a[4],
                                        unsigned b0, unsigned b1) {
    asm volatile("mma.sync.aligned.m16n8k16.row.col.f32.f16.f16.f32 "
                 "{%0,%1,%2,%3},{%4,%5,%6,%7},{%8,%9},{%0,%1,%2,%3};"
                 : "+f"(c[0]), "+f"(c[1]), "+f"(c[2]), "+f"(c[3])
                 : "r"(a[0]), "r"(a[1]), "r"(a[2]), "r"(a[3]), "r"(b0), "r"(b1));
}
__device__ __forceinline__ void cp16(unsigned saddr, const void* g) {
    asm volatile("cp.async.cg.shared.global [%0],[%1],16;" :: "r"(saddr), "l"(g));
}
__device__ __forceinline__ void cp_commit() {
    asm volatile("cp.async.commit_group;");
}
template <int N>
__device__ __forceinline__ void cp_wait() {
    asm volatile("cp.async.wait_group %0;" :: "n"(N));
}
__device__ __forceinline__ unsigned pack_h2(float a, float b) {
    __half2 h = __floats2half2_rn(a, b);
    return *reinterpret_cast<unsigned*>(&h);
}

// =====================================================================
// fp32 -> fp16 convert (grid-stride, float4 granularity)
// =====================================================================
__global__ void f2h_kernel(const float* __restrict__ src,
                           __half* __restrict__ dst, long n)
{
    long i = ((long)blockIdx.x * blockDim.x + threadIdx.x) * 4;
    long stride = (long)gridDim.x * blockDim.x * 4;
    for (; i < n; i += stride) {
        float4 v = *(const float4*)(src + i);
        __half2 h0 = __floats2half2_rn(v.x, v.y);
        __half2 h1 = __floats2half2_rn(v.z, v.w);
        *(__half2*)(dst + i)     = h0;
        *(__half2*)(dst + i + 2) = h1;
    }
}

// =====================================================================
// fp16 tensor-core GEMM: C[M,N](f32) = A[M,K](h) * B[N,K](h)^T
// 128x128 block, BK=64, 3-stage cp.async pipeline, 256 threads.
// smem stride 72 halves (144B): conflict-free LDSM, 16B aligned.
// =====================================================================
#define GSTRH 72
#define STAGE_H (256 * GSTRH)             // halves per stage (A128 + B128 rows)
#define GS 3
#define GEMM_SMEM (GS * STAGE_H * 2)      // 110592 B

__global__ __launch_bounds__(256, 2) void gemm_h16(
    const __half* __restrict__ A, const __half* __restrict__ B,
    float* __restrict__ C, int M, int N, int K)
{
    extern __shared__ __half smh[];

    int tid = threadIdx.x;
    int lane = tid & 31, warp = tid >> 5;
    int gid = lane >> 2, tig = lane & 3;
    int wm = warp >> 2, wn = warp & 3;
    int m0 = blockIdx.y * 128, n0 = blockIdx.x * 128;

    // global load mapping: chunk col fixed per thread, rows step by 32
    int ch   = tid & 7;        // 16B chunk (8 halves)
    int row0 = tid >> 3;       // 0..31
    const __half* gsrc[8];
#pragma unroll
    for (int i = 0; i < 8; i++) {
        int row = row0 + 32 * i;
        gsrc[i] = (row < 128 ? A + (long)(m0 + row) * K
                             : B + (long)(n0 + row - 128) * K) + ch * 8;
    }
    unsigned sdst[8];
#pragma unroll
    for (int i = 0; i < 8; i++)
        sdst[i] = smem_u32(smh + (row0 + 32 * i) * GSTRH + ch * 8);

    float acc[4][4][4];
#pragma unroll
    for (int mt = 0; mt < 4; mt++)
#pragma unroll
        for (int nt = 0; nt < 4; nt++)
#pragma unroll
            for (int r = 0; r < 4; r++) acc[mt][nt][r] = 0.f;

    int nk = K >> 6;   // 64-wide k tiles

    // prologue: stages 0, 1
#pragma unroll
    for (int s = 0; s < 2; s++) {
#pragma unroll
        for (int i = 0; i < 8; i++)
            cp16(sdst[i] + s * (STAGE_H * 2), gsrc[i] + (long)s * 64);
        cp_commit();
    }

    for (int k = 0; k < nk; k++) {
        cp_wait<1>();
        __syncthreads();

        // issue loads for stage k+2
        if (k + 2 < nk) {
            int sb = ((k + 2) % GS) * (STAGE_H * 2);
            long kof = (long)(k + 2) * 64;
#pragma unroll
            for (int i = 0; i < 8; i++)
                cp16(sdst[i] + sb, gsrc[i] + kof);
        }
        cp_commit();

        // compute stage k
        const __half* Ac = smh + (k % GS) * STAGE_H;
        const __half* Bc = Ac + 128 * GSTRH;
#pragma unroll
        for (int kc = 0; kc < 4; kc++) {
            unsigned aq[4][4], bk[2][4];
#pragma unroll
            for (int mt = 0; mt < 4; mt++) {
                int row = wm * 64 + mt * 16 + (lane & 15);
                int c2  = kc * 2 + (lane >> 4);
                ldsm4(aq[mt], smem_u32(Ac + row * GSTRH + c2 * 8));
            }
#pragma unroll
            for (int ntp = 0; ntp < 2; ntp++) {
                int row = wn * 32 + ntp * 16 + (lane & 7) + ((lane >> 4) << 3);
                int c2  = kc * 2 + ((lane >> 3) & 1);
                ldsm4(bk[ntp], smem_u32(Bc + row * GSTRH + c2 * 8));
            }
#pragma unroll
            for (int mt = 0; mt < 4; mt++)
#pragma unroll
                for (int ntp = 0; ntp < 2; ntp++) {
                    mma_f16(acc[mt][2*ntp],   aq[mt], bk[ntp][0], bk[ntp][1]);
                    mma_f16(acc[mt][2*ntp+1], aq[mt], bk[ntp][2], bk[ntp][3]);
                }
        }
        __syncthreads();
    }

    // epilogue
#pragma unroll
    for (int mt = 0; mt < 4; mt++) {
        int row = m0 + wm * 64 + mt * 16 + gid;
#pragma unroll
        for (int nt = 0; nt < 4; nt++) {
            int col = n0 + wn * 32 + nt * 8 + 2 * tig;
            *(float2*)&C[(long)row * N + col] = make_float2(acc[mt][nt][0], acc[mt][nt][1]);
            *(float2*)&C[(long)(row + 8) * N + col] = make_float2(acc[mt][nt][2], acc[mt][nt][3]);
        }
    }
}

// =====================================================================
// Fused per-head RMSNorm + RoPE + fp16 conversion into head-major bufs.
// grid = (T, 48): 0..31 q heads, 32..39 k heads, 40..47 v heads.
// q written pre-scaled by 1/sqrt(D).
// =====================================================================
__global__ void rmsnorm_rope_kernel(
    const float* __restrict__ qkv, const int* __restrict__ positions,
    const float* __restrict__ qw, const float* __restrict__ kw,
    __half* __restrict__ q16, __half* __restrict__ k16, __half* __restrict__ v16)
{
    int t  = blockIdx.x;
    int hh = blockIdx.y;
    int d  = threadIdx.x;          // 0..127

    if (hh >= NHEADS + NKV) {      // v head: plain convert
        int vh = hh - NHEADS - NKV;
        float v = qkv[(long)t * QKVW + QSIZE + KVSIZE + vh * HDIM + d];
        v16[((long)vh * T + t) * HDIM + d] = __float2half_rn(v);
        return;
    }

    bool isq = (hh < NHEADS);
    int off = isq ? hh * HDIM : QSIZE + (hh - NHEADS) * HDIM;
    const float* w = isq ? qw : kw;
    const float* x = qkv + (long)t * QKVW + off;
    __half* outp = isq ? (q16 + ((long)hh * T + t) * HDIM)
                       : (k16 + ((long)(hh - NHEADS) * T + t) * HDIM);
    float oscale = isq ? SCALING : 1.0f;

    float v = x[d];
    float ss = v * v;
#pragma unroll
    for (int o = 16; o >= 1; o >>= 1)
        ss += __shfl_xor_sync(0xffffffffu, ss, o);

    __shared__ float sred[4];
    __shared__ float snorm;
    __shared__ float sx[HDIM];
    int lane = d & 31, wp = d >> 5;
    if (lane == 0) sred[wp] = ss;
    __syncthreads();
    if (d == 0) {
        float tot = sred[0] + sred[1] + sred[2] + sred[3];
        snorm = rsqrtf(tot / (float)HDIM + 1e-6f);
    }
    __syncthreads();

    float nv = v * snorm * w[d];
    sx[d] = nv;
    __syncthreads();

    if (d < 64) {
        float x1 = sx[d];
        float x2 = sx[d + 64];
        float pos = (float)positions[t];
        float invf = powf(10000.0f, -((float)d) / 64.0f);
        float ang = pos * invf;
        float c, s;
        sincosf(ang, &s, &c);
        outp[d]      = __float2half_rn((x1 * c - x2 * s) * oscale);
        outp[d + 64] = __float2half_rn((x2 * c + x1 * s) * oscale);
    }
}

// =====================================================================
// fp16 flash attention (causal, GQA). Output fp16.
// Block: 128 q rows x 1 head, 8 warps (16 rows each). BKV=64.
// KV double-buffered via cp.async. P stays in registers.
// =====================================================================
#define FSTR 136
#define FQ_H (128 * FSTR)
#define FKV_H (64 * FSTR)
#define FLASH_SMEM ((FQ_H + 4 * FKV_H) * 2)   // 104448 B

__global__ __launch_bounds__(256, 2) void flash_h16(
    const __half* __restrict__ Q, const __half* __restrict__ Kh,
    const __half* __restrict__ Vh, __half* __restrict__ O)
{
    int qb = blockIdx.x;
    int h  = blockIdx.y;
    int kvh = h >> 2;
    int q0 = qb * 128;

    extern __shared__ __half smf[];
    __half* Qs = smf;                 // [128][136]
    __half* Ks = smf + FQ_H;          // [2][64][136]
    __half* Vs = Ks + 2 * FKV_H;      // [2][64][136]

    int tid = threadIdx.x;
    int lane = tid & 31, warp = tid >> 5;
    int gid = lane >> 2, tig = lane & 3;

    const __half* Qg = Q + ((long)h * T + q0) * HDIM;
    const __half* Kg = Kh + (long)kvh * T * HDIM;
    const __half* Vg = Vh + (long)kvh * T * HDIM;

    // prologue: Q tile (128 rows x 16 chunks), 8 chunks per thread
#pragma unroll
    for (int i = 0; i < 8; i++) {
        int idx = tid + i * 256;
        int r = idx >> 4, c = idx & 15;
        cp16(smem_u32(Qs + r * FSTR + c * 8), Qg + r * HDIM + c * 8);
    }
    // KV block 0
#pragma unroll
    for (int i = 0; i < 4; i++) {
        int idx = tid + i * 256;
        int r = idx >> 4, c = idx & 15;
        cp16(smem_u32(Ks + r * FSTR + c * 8), Kg + (long)r * HDIM + c * 8);
        cp16(smem_u32(Vs + r * FSTR + c * 8), Vg + (long)r * HDIM + c * 8);
    }
    cp_commit();

    float m0s = -1e30f, m1s = -1e30f, l0s = 0.f, l1s = 0.f;
    float oacc[16][4];
#pragma unroll
    for (int nt = 0; nt < 16; nt++)
#pragma unroll
        for (int r = 0; r < 4; r++) oacc[nt][r] = 0.f;

    int r0 = q0 + warp * 16 + gid;
    int r1 = r0 + 8;
    int kbmax = 2 * qb + 1;

    for (int kb = 0; kb <= kbmax; kb++) {
        cp_wait<0>();
        __syncthreads();

        // prefetch next KV block into the other buffer
        if (kb < kbmax) {
            __half* Kn = Ks + ((kb + 1) & 1) * FKV_H;
            __half* Vn = Vs + ((kb + 1) & 1) * FKV_H;
            long rowoff = (long)(kb + 1) * 64;
#pragma unroll
            for (int i = 0; i < 4; i++) {
                int idx = tid + i * 256;
                int r = idx >> 4, c = idx & 15;
                cp16(smem_u32(Kn + r * FSTR + c * 8), Kg + (rowoff + r) * HDIM + c * 8);
                cp16(smem_u32(Vn + r * FSTR + c * 8), Vg + (rowoff + r) * HDIM + c * 8);
            }
        }
        cp_commit();

        const __half* Kc = Ks + (kb & 1) * FKV_H;
        const __half* Vc = Vs + (kb & 1) * FKV_H;

        // ---- S = Q K^T ----
        float sacc[8][4];
#pragma unroll
        for (int nt = 0; nt < 8; nt++)
#pragma unroll
            for (int r = 0; r < 4; r++) sacc[nt][r] = 0.f;

#pragma unroll
        for (int kc = 0; kc < 8; kc++) {
            unsigned aq[4];
            {
                int row = warp * 16 + (lane & 15);
                int c2  = kc * 2 + (lane >> 4);
                ldsm4(aq, smem_u32(Qs + row * FSTR + c2 * 8));
            }
#pragma unroll
            for (int ntp = 0; ntp < 4; ntp++) {
                unsigned bk[4];
                int row = ntp * 16 + (lane & 7) + ((lane >> 4) << 3);
                int c2  = kc * 2 + ((lane >> 3) & 1);
                ldsm4(bk, smem_u32(Kc + row * FSTR + c2 * 8));
                mma_f16(sacc[2*ntp],   aq, bk[0], bk[1]);
                mma_f16(sacc[2*ntp+1], aq, bk[2], bk[3]);
            }
        }

        // ---- causal mask (last two kv blocks only) ----
        if (kb >= 2 * qb) {
#pragma unroll
            for (int nt = 0; nt < 8; nt++) {
                int colb = kb * 64 + nt * 8 + 2 * tig;
                if (colb > r0)     sacc[nt][0] = -1e30f;
                if (colb + 1 > r0) sacc[nt][1] = -1e30f;
                if (colb > r1)     sacc[nt][2] = -1e30f;
                if (colb + 1 > r1) sacc[nt][3] = -1e30f;
            }
        }

        // ---- online softmax ----
        float mx0 = -1e30f, mx1 = -1e30f;
#pragma unroll
        for (int nt = 0; nt < 8; nt++) {
            mx0 = fmaxf(mx0, fmaxf(sacc[nt][0], sacc[nt][1]));
            mx1 = fmaxf(mx1, fmaxf(sacc[nt][2], sacc[nt][3]));
        }
        mx0 = fmaxf(mx0, __shfl_xor_sync(0xffffffffu, mx0, 1));
        mx0 = fmaxf(mx0, __shfl_xor_sync(0xffffffffu, mx0, 2));
        mx1 = fmaxf(mx1, __shfl_xor_sync(0xffffffffu, mx1, 1));
        mx1 = fmaxf(mx1, __shfl_xor_sync(0xffffffffu, mx1, 2));

        float mn0 = fmaxf(m0s, mx0);
        float mn1 = fmaxf(m1s, mx1);
        float corr0 = __expf(m0s - mn0);
        float corr1 = __expf(m1s - mn1);

        float ls0 = 0.f, ls1 = 0.f;
#pragma unroll
        for (int nt = 0; nt < 8; nt++) {
            sacc[nt][0] = __expf(sacc[nt][0] - mn0);
            sacc[nt][1] = __expf(sacc[nt][1] - mn0);
            sacc[nt][2] = __expf(sacc[nt][2] - mn1);
            sacc[nt][3] = __expf(sacc[nt][3] - mn1);
            ls0 += sacc[nt][0] + sacc[nt][1];
            ls1 += sacc[nt][2] + sacc[nt][3];
        }
        ls0 += __shfl_xor_sync(0xffffffffu, ls0, 1);
        ls0 += __shfl_xor_sync(0xffffffffu, ls0, 2);
        ls1 += __shfl_xor_sync(0xffffffffu, ls1, 1);
        ls1 += __shfl_xor_sync(0xffffffffu, ls1, 2);

        l0s = l0s * corr0 + ls0;
        l1s = l1s * corr1 + ls1;
        m0s = mn0;
        m1s = mn1;

#pragma unroll
        for (int nt = 0; nt < 16; nt++) {
            oacc[nt][0] *= corr0;
            oacc[nt][1] *= corr0;
            oacc[nt][2] *= corr1;
            oacc[nt][3] *= corr1;
        }

        // ---- O += P V (P from registers) ----
#pragma unroll
        for (int kc2 = 0; kc2 < 4; kc2++) {
            unsigned ap[4];
            ap[0] = pack_h2(sacc[2*kc2][0],   sacc[2*kc2][1]);
            ap[1] = pack_h2(sacc[2*kc2][2],   sacc[2*kc2][3]);
            ap[2] = pack_h2(sacc[2*kc2+1][0], sacc[2*kc2+1][1]);
            ap[3] = pack_h2(sacc[2*kc2+1][2], sacc[2*kc2+1][3]);
#pragma unroll
            for (int ntp = 0; ntp < 8; ntp++) {
                unsigned bv[4];
                int row = kc2 * 16 + (lane & 7) + (((lane >> 3) & 1) << 3);
                int c2  = ntp * 2 + (lane >> 4);
                ldsm4t(bv, smem_u32(Vc + row * FSTR + c2 * 8));
                mma_f16(oacc[2*ntp],   ap, bv[0], bv[1]);
                mma_f16(oacc[2*ntp+1], ap, bv[2], bv[3]);
            }
        }
    }

    // epilogue (fp16 out)
    float inv0 = 1.0f / l0s;
    float inv1 = 1.0f / l1s;
#pragma unroll
    for (int nt = 0; nt < 16; nt++) {
        int col = h * HDIM + nt * 8 + 2 * tig;
        *(__half2*)&O[(long)r0 * QSIZE + col] =
            __floats2half2_rn(oacc[nt][0] * inv0, oacc[nt][1] * inv0);
        *(__half2*)&O[(long)r1 * QSIZE + col] =
            __floats2half2_rn(oacc[nt][2] * inv1, oacc[nt][3] * inv1);
    }
}

// =====================================================================
// launch
// =====================================================================
extern "C" void kernel_launch(void* const* d_in, const int* in_sizes, int n_in,
                              void* d_out, int out_size)
{
    const int*   positions = (const int*)d_in[0];
    const float* hidden    = (const float*)d_in[1];
    const float* wqkv      = (const float*)d_in[2];
    const float* wo        = (const float*)d_in[3];
    const float* qnw       = (const float*)d_in[4];
    const float* knw       = (const float*)d_in[5];
    float* out = (float*)d_out;

    float *qkv = nullptr;
    __half *h16, *wqkv16, *wo16, *q16, *k16, *v16, *o16;
    cudaGetSymbolAddress((void**)&qkv, g_qkv);
    cudaGetSymbolAddress((void**)&h16, g_h16);
    cudaGetSymbolAddress((void**)&wqkv16, g_wqkv16);
    cudaGetSymbolAddress((void**)&wo16, g_wo16);
    cudaGetSymbolAddress((void**)&q16, g_q16);
    cudaGetSymbolAddress((void**)&k16, g_k16);
    cudaGetSymbolAddress((void**)&v16, g_v16);
    cudaGetSymbolAddress((void**)&o16, g_o16);

    static bool attr_done = false;
    if (!attr_done) {
        cudaFuncSetAttribute(gemm_h16,
                             cudaFuncAttributeMaxDynamicSharedMemorySize, GEMM_SMEM);
        cudaFuncSetAttribute(flash_h16,
                             cudaFuncAttributeMaxDynamicSharedMemorySize, FLASH_SMEM);
        attr_done = true;
    }

    // 0) fp32 -> fp16 converts (hidden, wqkv, wo)
    f2h_kernel<<<2048, 256>>>(hidden, h16, (long)T * HIDDEN);
    f2h_kernel<<<4096, 256>>>(wqkv, wqkv16, (long)QKVW * HIDDEN);
    f2h_kernel<<<4096, 256>>>(wo, wo16, (long)HIDDEN * QSIZE);

    // 1) qkv = hidden @ wqkv^T   [2048, 6144]
    {
        dim3 grid(QKVW / 128, T / 128);
        gemm_h16<<<grid, 256, GEMM_SMEM>>>(h16, wqkv16, qkv, T, QKVW, HIDDEN);
    }
    // 2) rmsnorm + rope + fp16 head-major repack (q scaled)
    {
        dim3 grid(T, NHEADS + 2 * NKV);
        rmsnorm_rope_kernel<<<grid, 128>>>(qkv, positions, qnw, knw, q16, k16, v16);
    }
    // 3) causal flash attention -> o16 [2048, 4096] fp16
    {
        dim3 grid(T / 128, NHEADS);
        flash_h16<<<grid, 256, FLASH_SMEM>>>(q16, k16, v16, o16);
    }
    // 4) out = o @ wo^T   [2048, 2048]
    {
        dim3 grid(HIDDEN / 128, T / 128);
        gemm_h16<<<grid, 256, GEMM_SMEM>>>(o16, wo16, out, T, HIDDEN, QSIZE);
    }
}

// round 5
// speedup vs baseline: 10.5083x; 1.0013x over previous
#include <cuda_runtime.h>
#include <cuda_fp16.h>
#include <math.h>

// ---------------- constants ----------------
#define T        2048
#define HIDDEN   2048
#define NHEADS   32
#define NKV      8
#define HDIM     128
#define QSIZE    (NHEADS * HDIM)          // 4096
#define KVSIZE   (NKV * HDIM)             // 1024
#define QKVW     (QSIZE + 2 * KVSIZE)     // 6144
#define SCALING  0.08838834764831845f     // 1/sqrt(128)

// ---------------- scratch (no allocations allowed) ----------------
__device__ float  g_qkv[T * QKVW];             // fp32 qkv (gemm out, norm in)
__device__ __half g_h16[T * HIDDEN];           // hidden fp16
__device__ __half g_wqkv16[QKVW * HIDDEN];     // wqkv fp16
__device__ __half g_wo16[HIDDEN * QSIZE];      // wo fp16
__device__ __half g_q16[NHEADS * T * HDIM];    // head-major, scaled
__device__ __half g_k16[NKV * T * HDIM];       // head-major
__device__ __half g_v16[NKV * T * HDIM];       // head-major
__device__ __half g_o16[T * QSIZE];            // attention out fp16

// ---------------- ptx helpers ----------------
__device__ __forceinline__ unsigned smem_u32(const void* p) {
    return (unsigned)__cvta_generic_to_shared(p);
}
__device__ __forceinline__ void ldsm4(unsigned r[4], unsigned addr) {
    asm volatile("ldmatrix.sync.aligned.m8n8.x4.shared.b16 {%0,%1,%2,%3},[%4];"
                 : "=r"(r[0]), "=r"(r[1]), "=r"(r[2]), "=r"(r[3]) : "r"(addr));
}
__device__ __forceinline__ void ldsm4t(unsigned r[4], unsigned addr) {
    asm volatile("ldmatrix.sync.aligned.m8n8.x4.trans.shared.b16 {%0,%1,%2,%3},[%4];"
                 : "=r"(r[0]), "=r"(r[1]), "=r"(r[2]), "=r"(r[3]) : "r"(addr));
}
__device__ __forceinline__ void mma_f16(float c[4], const unsigned a[4],
                                        unsigned b0, unsigned b1) {
    asm volatile("mma.sync.aligned.m16n8k16.row.col.f32.f16.f16.f32 "
                 "{%0,%1,%2,%3},{%4,%5,%6,%7},{%8,%9},{%0,%1,%2,%3};"
                 : "+f"(c[0]), "+f"(c[1]), "+f"(c[2]), "+f"(c[3])
                 : "r"(a[0]), "r"(a[1]), "r"(a[2]), "r"(a[3]), "r"(b0), "r"(b1));
}
__device__ __forceinline__ void cp16(unsigned saddr, const void* g) {
    asm volatile("cp.async.cg.shared.global [%0],[%1],16;" :: "r"(saddr), "l"(g));
}
__device__ __forceinline__ void cp_commit() {
    asm volatile("cp.async.commit_group;");
}
template <int N>
__device__ __forceinline__ void cp_wait() {
    asm volatile("cp.async.wait_group %0;" :: "n"(N));
}
__device__ __forceinline__ unsigned pack_h2(float a, float b) {
    __half2 h = __floats2half2_rn(a, b);
    return *reinterpret_cast<unsigned*>(&h);
}

// =====================================================================
// fp32 -> fp16 convert (grid-stride, float4 granularity)
// =====================================================================
__global__ void f2h_kernel(const float* __restrict__ src,
                           __half* __restrict__ dst, long n)
{
    long i = ((long)blockIdx.x * blockDim.x + threadIdx.x) * 4;
    long stride = (long)gridDim.x * blockDim.x * 4;
    for (; i < n; i += stride) {
        float4 v = *(const float4*)(src + i);
        __half2 h0 = __floats2half2_rn(v.x, v.y);
        __half2 h1 = __floats2half2_rn(v.z, v.w);
        *(__half2*)(dst + i)     = h0;
        *(__half2*)(dst + i + 2) = h1;
    }
}

// =====================================================================
// fp16 tensor-core GEMM: C[M,N](f32) = A[M,K](h) * B[N,K](h)^T
// 128x128 block, BK=64, 3-stage cp.async pipeline, 256 threads.
// smem stride 72 halves (144B): conflict-free LDSM, 16B aligned.
// =====================================================================
#define GSTRH 72
#define STAGE_H (256 * GSTRH)             // halves per stage (A128 + B128 rows)
#define GS 3
#define GEMM_SMEM (GS * STAGE_H * 2)      // 110592 B

__global__ __launch_bounds__(256, 2) void gemm_h16(
    const __half* __restrict__ A, const __half* __restrict__ B,
    float* __restrict__ C, int M, int N, int K)
{
    extern __shared__ __half smh[];

    int tid = threadIdx.x;
    int lane = tid & 31, warp = tid >> 5;
    int gid = lane >> 2, tig = lane & 3;
    int wm = warp >> 2, wn = warp & 3;
    int m0 = blockIdx.y * 128, n0 = blockIdx.x * 128;

    // global load mapping: chunk col fixed per thread, rows step by 32
    int ch   = tid & 7;        // 16B chunk (8 halves)
    int row0 = tid >> 3;       // 0..31
    const __half* gsrc[8];
#pragma unroll
    for (int i = 0; i < 8; i++) {
        int row = row0 + 32 * i;
        gsrc[i] = (row < 128 ? A + (long)(m0 + row) * K
                             : B + (long)(n0 + row - 128) * K) + ch * 8;
    }
    unsigned sdst[8];
#pragma unroll
    for (int i = 0; i < 8; i++)
        sdst[i] = smem_u32(smh + (row0 + 32 * i) * GSTRH + ch * 8);

    float acc[4][4][4];
#pragma unroll
    for (int mt = 0; mt < 4; mt++)
#pragma unroll
        for (int nt = 0; nt < 4; nt++)
#pragma unroll
            for (int r = 0; r < 4; r++) acc[mt][nt][r] = 0.f;

    int nk = K >> 6;   // 64-wide k tiles

    // prologue: stages 0, 1
#pragma unroll
    for (int s = 0; s < 2; s++) {
#pragma unroll
        for (int i = 0; i < 8; i++)
            cp16(sdst[i] + s * (STAGE_H * 2), gsrc[i] + (long)s * 64);
        cp_commit();
    }

    for (int k = 0; k < nk; k++) {
        cp_wait<1>();
        __syncthreads();

        // issue loads for stage k+2
        if (k + 2 < nk) {
            int sb = ((k + 2) % GS) * (STAGE_H * 2);
            long kof = (long)(k + 2) * 64;
#pragma unroll
            for (int i = 0; i < 8; i++)
                cp16(sdst[i] + sb, gsrc[i] + kof);
        }
        cp_commit();

        // compute stage k
        const __half* Ac = smh + (k % GS) * STAGE_H;
        const __half* Bc = Ac + 128 * GSTRH;
#pragma unroll
        for (int kc = 0; kc < 4; kc++) {
            unsigned aq[4][4], bk[2][4];
#pragma unroll
            for (int mt = 0; mt < 4; mt++) {
                int row = wm * 64 + mt * 16 + (lane & 15);
                int c2  = kc * 2 + (lane >> 4);
                ldsm4(aq[mt], smem_u32(Ac + row * GSTRH + c2 * 8));
            }
#pragma unroll
            for (int ntp = 0; ntp < 2; ntp++) {
                int row = wn * 32 + ntp * 16 + (lane & 7) + ((lane >> 4) << 3);
                int c2  = kc * 2 + ((lane >> 3) & 1);
                ldsm4(bk[ntp], smem_u32(Bc + row * GSTRH + c2 * 8));
            }
#pragma unroll
            for (int mt = 0; mt < 4; mt++)
#pragma unroll
                for (int ntp = 0; ntp < 2; ntp++) {
                    mma_f16(acc[mt][2*ntp],   aq[mt], bk[ntp][0], bk[ntp][1]);
                    mma_f16(acc[mt][2*ntp+1], aq[mt], bk[ntp][2], bk[ntp][3]);
                }
        }
        __syncthreads();
    }

    // epilogue
#pragma unroll
    for (int mt = 0; mt < 4; mt++) {
        int row = m0 + wm * 64 + mt * 16 + gid;
#pragma unroll
        for (int nt = 0; nt < 4; nt++) {
            int col = n0 + wn * 32 + nt * 8 + 2 * tig;
            *(float2*)&C[(long)row * N + col] = make_float2(acc[mt][nt][0], acc[mt][nt][1]);
            *(float2*)&C[(long)(row + 8) * N + col] = make_float2(acc[mt][nt][2], acc[mt][nt][3]);
        }
    }
}

// =====================================================================
// Fused per-head RMSNorm + RoPE + fp16 conversion into head-major bufs.
// grid = (T, 48): 0..31 q heads, 32..39 k heads, 40..47 v heads.
// q written pre-scaled by 1/sqrt(D).
// =====================================================================
__global__ void rmsnorm_rope_kernel(
    const float* __restrict__ qkv, const int* __restrict__ positions,
    const float* __restrict__ qw, const float* __restrict__ kw,
    __half* __restrict__ q16, __half* __restrict__ k16, __half* __restrict__ v16)
{
    int t  = blockIdx.x;
    int hh = blockIdx.y;
    int d  = threadIdx.x;          // 0..127

    if (hh >= NHEADS + NKV) {      // v head: plain convert
        int vh = hh - NHEADS - NKV;
        float v = qkv[(long)t * QKVW + QSIZE + KVSIZE + vh * HDIM + d];
        v16[((long)vh * T + t) * HDIM + d] = __float2half_rn(v);
        return;
    }

    bool isq = (hh < NHEADS);
    int off = isq ? hh * HDIM : QSIZE + (hh - NHEADS) * HDIM;
    const float* w = isq ? qw : kw;
    const float* x = qkv + (long)t * QKVW + off;
    __half* outp = isq ? (q16 + ((long)hh * T + t) * HDIM)
                       : (k16 + ((long)(hh - NHEADS) * T + t) * HDIM);
    float oscale = isq ? SCALING : 1.0f;

    float v = x[d];
    float ss = v * v;
#pragma unroll
    for (int o = 16; o >= 1; o >>= 1)
        ss += __shfl_xor_sync(0xffffffffu, ss, o);

    __shared__ float sred[4];
    __shared__ float snorm;
    __shared__ float sx[HDIM];
    int lane = d & 31, wp = d >> 5;
    if (lane == 0) sred[wp] = ss;
    __syncthreads();
    if (d == 0) {
        float tot = sred[0] + sred[1] + sred[2] + sred[3];
        snorm = rsqrtf(tot / (float)HDIM + 1e-6f);
    }
    __syncthreads();

    float nv = v * snorm * w[d];
    sx[d] = nv;
    __syncthreads();

    if (d < 64) {
        float x1 = sx[d];
        float x2 = sx[d + 64];
        float pos = (float)positions[t];
        float invf = powf(10000.0f, -((float)d) / 64.0f);
        float ang = pos * invf;
        float c, s;
        sincosf(ang, &s, &c);
        outp[d]      = __float2half_rn((x1 * c - x2 * s) * oscale);
        outp[d + 64] = __float2half_rn((x2 * c + x1 * s) * oscale);
    }
}

// =====================================================================
// fp16 flash attention (causal, GQA). Output fp16.
// Block: 128 q rows x 1 head, 8 warps (16 rows each). BKV=64.
// KV double-buffered via cp.async. P stays in registers.
// =====================================================================
#define FSTR 136
#define FQ_H (128 * FSTR)
#define FKV_H (64 * FSTR)
#define FLASH_SMEM ((FQ_H + 4 * FKV_H) * 2)   // 104448 B

__global__ __launch_bounds__(256, 2) void flash_h16(
    const __half* __restrict__ Q, const __half* __restrict__ Kh,
    const __half* __restrict__ Vh, __half* __restrict__ O)
{
    int qb = blockIdx.x;
    int h  = blockIdx.y;
    int kvh = h >> 2;
    int q0 = qb * 128;

    extern __shared__ __half smf[];
    __half* Qs = smf;                 // [128][136]
    __half* Ks = smf + FQ_H;          // [2][64][136]
    __half* Vs = Ks + 2 * FKV_H;      // [2][64][136]

    int tid = threadIdx.x;
    int lane = tid & 31, warp = tid >> 5;
    int gid = lane >> 2, tig = lane & 3;

    const __half* Qg = Q + ((long)h * T + q0) * HDIM;
    const __half* Kg = Kh + (long)kvh * T * HDIM;
    const __half* Vg = Vh + (long)kvh * T * HDIM;

    // prologue: Q tile (128 rows x 16 chunks), 8 chunks per thread
#pragma unroll
    for (int i = 0; i < 8; i++) {
        int idx = tid + i * 256;
        int r = idx >> 4, c = idx & 15;
        cp16(smem_u32(Qs + r * FSTR + c * 8), Qg + r * HDIM + c * 8);
    }
    // KV block 0
#pragma unroll
    for (int i = 0; i < 4; i++) {
        int idx = tid + i * 256;
        int r = idx >> 4, c = idx & 15;
        cp16(smem_u32(Ks + r * FSTR + c * 8), Kg + (long)r * HDIM + c * 8);
        cp16(smem_u32(Vs + r * FSTR + c * 8), Vg + (long)r * HDIM + c * 8);
    }
    cp_commit();

    float m0s = -1e30f, m1s = -1e30f, l0s = 0.f, l1s = 0.f;
    float oacc[16][4];
#pragma unroll
    for (int nt = 0; nt < 16; nt++)
#pragma unroll
        for (int r = 0; r < 4; r++) oacc[nt][r] = 0.f;

    int r0 = q0 + warp * 16 + gid;
    int r1 = r0 + 8;
    int kbmax = 2 * qb + 1;

    for (int kb = 0; kb <= kbmax; kb++) {
        cp_wait<0>();
        __syncthreads();

        // prefetch next KV block into the other buffer
        if (kb < kbmax) {
            __half* Kn = Ks + ((kb + 1) & 1) * FKV_H;
            __half* Vn = Vs + ((kb + 1) & 1) * FKV_H;
            long rowoff = (long)(kb + 1) * 64;
#pragma unroll
            for (int i = 0; i < 4; i++) {
                int idx = tid + i * 256;
                int r = idx >> 4, c = idx & 15;
                cp16(smem_u32(Kn + r * FSTR + c * 8), Kg + (rowoff + r) * HDIM + c * 8);
                cp16(smem_u32(Vn + r * FSTR + c * 8), Vg + (rowoff + r) * HDIM + c * 8);
            }
        }
        cp_commit();

        const __half* Kc = Ks + (kb & 1) * FKV_H;
        const __half* Vc = Vs + (kb & 1) * FKV_H;

        // ---- S = Q K^T ----
        float sacc[8][4];
#pragma unroll
        for (int nt = 0; nt < 8; nt++)
#pragma unroll
            for (int r = 0; r < 4; r++) sacc[nt][r] = 0.f;

#pragma unroll
        for (int kc = 0; kc < 8; kc++) {
            unsigned aq[4];
            {
                int row = warp * 16 + (lane & 15);
                int c2  = kc * 2 + (lane >> 4);
                ldsm4(aq, smem_u32(Qs + row * FSTR + c2 * 8));
            }
#pragma unroll
            for (int ntp = 0; ntp < 4; ntp++) {
                unsigned bk[4];
                int row = ntp * 16 + (lane & 7) + ((lane >> 4) << 3);
                int c2  = kc * 2 + ((lane >> 3) & 1);
                ldsm4(bk, smem_u32(Kc + row * FSTR + c2 * 8));
                mma_f16(sacc[2*ntp],   aq, bk[0], bk[1]);
                mma_f16(sacc[2*ntp+1], aq, bk[2], bk[3]);
            }
        }

        // ---- causal mask (last two kv blocks only) ----
        if (kb >= 2 * qb) {
#pragma unroll
            for (int nt = 0; nt < 8; nt++) {
                int colb = kb * 64 + nt * 8 + 2 * tig;
                if (colb > r0)     sacc[nt][0] = -1e30f;
                if (colb + 1 > r0) sacc[nt][1] = -1e30f;
                if (colb > r1)     sacc[nt][2] = -1e30f;
                if (colb + 1 > r1) sacc[nt][3] = -1e30f;
            }
        }

        // ---- online softmax ----
        float mx0 = -1e30f, mx1 = -1e30f;
#pragma unroll
        for (int nt = 0; nt < 8; nt++) {
            mx0 = fmaxf(mx0, fmaxf(sacc[nt][0], sacc[nt][1]));
            mx1 = fmaxf(mx1, fmaxf(sacc[nt][2], sacc[nt][3]));
        }
        mx0 = fmaxf(mx0, __shfl_xor_sync(0xffffffffu, mx0, 1));
        mx0 = fmaxf(mx0, __shfl_xor_sync(0xffffffffu, mx0, 2));
        mx1 = fmaxf(mx1, __shfl_xor_sync(0xffffffffu, mx1, 1));
        mx1 = fmaxf(mx1, __shfl_xor_sync(0xffffffffu, mx1, 2));

        float mn0 = fmaxf(m0s, mx0);
        float mn1 = fmaxf(m1s, mx1);
        float corr0 = __expf(m0s - mn0);
        float corr1 = __expf(m1s - mn1);

        float ls0 = 0.f, ls1 = 0.f;
#pragma unroll
        for (int nt = 0; nt < 8; nt++) {
            sacc[nt][0] = __expf(sacc[nt][0] - mn0);
            sacc[nt][1] = __expf(sacc[nt][1] - mn0);
            sacc[nt][2] = __expf(sacc[nt][2] - mn1);
            sacc[nt][3] = __expf(sacc[nt][3] - mn1);
            ls0 += sacc[nt][0] + sacc[nt][1];
            ls1 += sacc[nt][2] + sacc[nt][3];
        }
        ls0 += __shfl_xor_sync(0xffffffffu, ls0, 1);
        ls0 += __shfl_xor_sync(0xffffffffu, ls0, 2);
        ls1 += __shfl_xor_sync(0xffffffffu, ls1, 1);
        ls1 += __shfl_xor_sync(0xffffffffu, ls1, 2);

        l0s = l0s * corr0 + ls0;
        l1s = l1s * corr1 + ls1;
        m0s = mn0;
        m1s = mn1;

#pragma unroll
        for (int nt = 0; nt < 16; nt++) {
            oacc[nt][0] *= corr0;
            oacc[nt][1] *= corr0;
            oacc[nt][2] *= corr1;
            oacc[nt][3] *= corr1;
        }

        // ---- O += P V (P from registers) ----
#pragma unroll
        for (int kc2 = 0; kc2 < 4; kc2++) {
            unsigned ap[4];
            ap[0] = pack_h2(sacc[2*kc2][0],   sacc[2*kc2][1]);
            ap[1] = pack_h2(sacc[2*kc2][2],   sacc[2*kc2][3]);
            ap[2] = pack_h2(sacc[2*kc2+1][0], sacc[2*kc2+1][1]);
            ap[3] = pack_h2(sacc[2*kc2+1][2], sacc[2*kc2+1][3]);
#pragma unroll
            for (int ntp = 0; ntp < 8; ntp++) {
                unsigned bv[4];
                int row = kc2 * 16 + (lane & 7) + (((lane >> 3) & 1) << 3);
                int c2  = ntp * 2 + (lane >> 4);
                ldsm4t(bv, smem_u32(Vc + row * FSTR + c2 * 8));
                mma_f16(oacc[2*ntp],   ap, bv[0], bv[1]);
                mma_f16(oacc[2*ntp+1], ap, bv[2], bv[3]);
            }
        }
    }

    // epilogue (fp16 out)
    float inv0 = 1.0f / l0s;
    float inv1 = 1.0f / l1s;
#pragma unroll
    for (int nt = 0; nt < 16; nt++) {
        int col = h * HDIM + nt * 8 + 2 * tig;
        *(__half2*)&O[(long)r0 * QSIZE + col] =
            __floats2half2_rn(oacc[nt][0] * inv0, oacc[nt][1] * inv0);
        *(__half2*)&O[(long)r1 * QSIZE + col] =
            __floats2half2_rn(oacc[nt][2] * inv1, oacc[nt][3] * inv1);
    }
}

// =====================================================================
// launch
// =====================================================================
extern "C" void kernel_launch(void* const* d_in, const int* in_sizes, int n_in,
                              void* d_out, int out_size)
{
    const int*   positions = (const int*)d_in[0];
    const float* hidden    = (const float*)d_in[1];
    const float* wqkv      = (const float*)d_in[2];
    const float* wo        = (const float*)d_in[3];
    const float* qnw       = (const float*)d_in[4];
    const float* knw       = (const float*)d_in[5];
    float* out = (float*)d_out;

    float *qkv = nullptr;
    __half *h16, *wqkv16, *wo16, *q16, *k16, *v16, *o16;
    cudaGetSymbolAddress((void**)&qkv, g_qkv);
    cudaGetSymbolAddress((void**)&h16, g_h16);
    cudaGetSymbolAddress((void**)&wqkv16, g_wqkv16);
    cudaGetSymbolAddress((void**)&wo16, g_wo16);
    cudaGetSymbolAddress((void**)&q16, g_q16);
    cudaGetSymbolAddress((void**)&k16, g_k16);
    cudaGetSymbolAddress((void**)&v16, g_v16);
    cudaGetSymbolAddress((void**)&o16, g_o16);

    static bool attr_done = false;
    if (!attr_done) {
        cudaFuncSetAttribute(gemm_h16,
                             cudaFuncAttributeMaxDynamicSharedMemorySize, GEMM_SMEM);
        cudaFuncSetAttribute(flash_h16,
                             cudaFuncAttributeMaxDynamicSharedMemorySize, FLASH_SMEM);
        attr_done = true;
    }

    // 0) fp32 -> fp16 converts (hidden, wqkv, wo)
    f2h_kernel<<<2048, 256>>>(hidden, h16, (long)T * HIDDEN);
    f2h_kernel<<<4096, 256>>>(wqkv, wqkv16, (long)QKVW * HIDDEN);
    f2h_kernel<<<4096, 256>>>(wo, wo16, (long)HIDDEN * QSIZE);

    // 1) qkv = hidden @ wqkv^T   [2048, 6144]
    {
        dim3 grid(QKVW / 128, T / 128);
        gemm_h16<<<grid, 256, GEMM_SMEM>>>(h16, wqkv16, qkv, T, QKVW, HIDDEN);
    }
    // 2) rmsnorm + rope + fp16 head-major repack (q scaled)
    {
        dim3 grid(T, NHEADS + 2 * NKV);
        rmsnorm_rope_kernel<<<grid, 128>>>(qkv, positions, qnw, knw, q16, k16, v16);
    }
    // 3) causal flash attention -> o16 [2048, 4096] fp16
    {
        dim3 grid(T / 128, NHEADS);
        flash_h16<<<grid, 256, FLASH_SMEM>>>(q16, k16, v16, o16);
    }
    // 4) out = o @ wo^T   [2048, 2048]
    {
        dim3 grid(HIDDEN / 128, T / 128);
        gemm_h16<<<grid, 256, GEMM_SMEM>>>(o16, wo16, out, T, HIDDEN, QSIZE);
    }
}

// round 7
// speedup vs baseline: 10.7611x; 1.0241x over previous
#include <cuda_runtime.h>
#include <cuda_fp16.h>
#include <math.h>

// ---------------- constants ----------------
#define T        2048
#define HIDDEN   2048
#define NHEADS   32
#define NKV      8
#define HDIM     128
#define QSIZE    (NHEADS * HDIM)          // 4096
#define KVSIZE   (NKV * HDIM)             // 1024
#define QKVW     (QSIZE + 2 * KVSIZE)     // 6144
#define SCALING  0.08838834764831845f     // 1/sqrt(128)
#define LOG2E    1.4426950408889634f

// ---------------- scratch (no allocations allowed) ----------------
__device__ __half g_qkv16[T * QKVW];           // fp16 qkv (gemm out)
__device__ __half g_h16[T * HIDDEN];           // hidden fp16
__device__ __half g_wqkv16[QKVW * HIDDEN];     // wqkv fp16
__device__ __half g_wo16[HIDDEN * QSIZE];      // wo fp16
__device__ __half g_q16[NHEADS * T * HDIM];    // head-major, scaled by 1/sqrt(D)*log2e
__device__ __half g_k16[NKV * T * HDIM];       // head-major
__device__ __half g_o16[T * QSIZE];            // attention out fp16

// ---------------- ptx helpers ----------------
__device__ __forceinline__ unsigned smem_u32(const void* p) {
    return (unsigned)__cvta_generic_to_shared(p);
}
__device__ __forceinline__ void ldsm4(unsigned r[4], unsigned addr) {
    asm volatile("ldmatrix.sync.aligned.m8n8.x4.shared.b16 {%0,%1,%2,%3},[%4];"
                 : "=r"(r[0]), "=r"(r[1]), "=r"(r[2]), "=r"(r[3]) : "r"(addr));
}
__device__ __forceinline__ void ldsm4t(unsigned r[4], unsigned addr) {
    asm volatile("ldmatrix.sync.aligned.m8n8.x4.trans.shared.b16 {%0,%1,%2,%3},[%4];"
                 : "=r"(r[0]), "=r"(r[1]), "=r"(r[2]), "=r"(r[3]) : "r"(addr));
}
__device__ __forceinline__ void mma_f16(float c[4], const unsigned a[4],
                                        unsigned b0, unsigned b1) {
    asm volatile("mma.sync.aligned.m16n8k16.row.col.f32.f16.f16.f32 "
                 "{%0,%1,%2,%3},{%4,%5,%6,%7},{%8,%9},{%0,%1,%2,%3};"
                 : "+f"(c[0]), "+f"(c[1]), "+f"(c[2]), "+f"(c[3])
                 : "r"(a[0]), "r"(a[1]), "r"(a[2]), "r"(a[3]), "r"(b0), "r"(b1));
}
__device__ __forceinline__ void cp16(unsigned saddr, const void* g) {
    asm volatile("cp.async.cg.shared.global [%0],[%1],16;" :: "r"(saddr), "l"(g));
}
__device__ __forceinline__ void cp_commit() {
    asm volatile("cp.async.commit_group;");
}
template <int N>
__device__ __forceinline__ void cp_wait() {
    asm volatile("cp.async.wait_group %0;" :: "n"(N));
}
__device__ __forceinline__ unsigned pack_h2(float a, float b) {
    __half2 h = __floats2half2_rn(a, b);
    return *reinterpret_cast<unsigned*>(&h);
}

// =====================================================================
// fp32 -> fp16 convert (grid-stride, float4 granularity)
// =====================================================================
__global__ void f2h_kernel(const float* __restrict__ src,
                           __half* __restrict__ dst, long n)
{
    long i = ((long)blockIdx.x * blockDim.x + threadIdx.x) * 4;
    long stride = (long)gridDim.x * blockDim.x * 4;
    for (; i < n; i += stride) {
        float4 v = *(const float4*)(src + i);
        *(__half2*)(dst + i)     = __floats2half2_rn(v.x, v.y);
        *(__half2*)(dst + i + 2) = __floats2half2_rn(v.z, v.w);
    }
}

// =====================================================================
// fp16 tensor-core GEMM: C[M,N] = A[M,K](h) * B[N,K](h)^T, OutT out.
// 128x128 block, BK=64, 3-stage cp.async pipeline, 256 threads.
// One barrier per k-iter (ring distance makes the 2nd redundant).
// =====================================================================
#define GSTRH 72
#define STAGE_H (256 * GSTRH)             // halves per stage (A128 + B128 rows)
#define GS 3
#define GEMM_SMEM (GS * STAGE_H * 2)      // 110592 B

template <typename OutT>
__global__ __launch_bounds__(256, 2) void gemm_h16(
    const __half* __restrict__ A, const __half* __restrict__ B,
    OutT* __restrict__ C, int M, int N, int K)
{
    extern __shared__ __half smh[];

    int tid = threadIdx.x;
    int lane = tid & 31, warp = tid >> 5;
    int gid = lane >> 2, tig = lane & 3;
    int wm = warp >> 2, wn = warp & 3;
    int m0 = blockIdx.y * 128, n0 = blockIdx.x * 128;

    int ch   = tid & 7;        // 16B chunk (8 halves)
    int row0 = tid >> 3;       // 0..31
    const __half* gsrc[8];
#pragma unroll
    for (int i = 0; i < 8; i++) {
        int row = row0 + 32 * i;
        gsrc[i] = (row < 128 ? A + (long)(m0 + row) * K
                             : B + (long)(n0 + row - 128) * K) + ch * 8;
    }
    unsigned sdst[8];
#pragma unroll
    for (int i = 0; i < 8; i++)
        sdst[i] = smem_u32(smh + (row0 + 32 * i) * GSTRH + ch * 8);

    float acc[4][4][4];
#pragma unroll
    for (int mt = 0; mt < 4; mt++)
#pragma unroll
        for (int nt = 0; nt < 4; nt++)
#pragma unroll
            for (int r = 0; r < 4; r++) acc[mt][nt][r] = 0.f;

    int nk = K >> 6;   // 64-wide k tiles

    // prologue: stages 0, 1
#pragma unroll
    for (int s = 0; s < 2; s++) {
#pragma unroll
        for (int i = 0; i < 8; i++)
            cp16(sdst[i] + s * (STAGE_H * 2), gsrc[i] + (long)s * 64);
        cp_commit();
    }

    for (int k = 0; k < nk; k++) {
        cp_wait<1>();
        __syncthreads();

        // issue loads for stage k+2 (ring distance guarantees safety)
        if (k + 2 < nk) {
            int sb = ((k + 2) % GS) * (STAGE_H * 2);
            long kof = (long)(k + 2) * 64;
#pragma unroll
            for (int i = 0; i < 8; i++)
                cp16(sdst[i] + sb, gsrc[i] + kof);
        }
        cp_commit();

        // compute stage k
        const __half* Ac = smh + (k % GS) * STAGE_H;
        const __half* Bc = Ac + 128 * GSTRH;
#pragma unroll
        for (int kc = 0; kc < 4; kc++) {
            unsigned aq[4][4], bk[2][4];
#pragma unroll
            for (int mt = 0; mt < 4; mt++) {
                int row = wm * 64 + mt * 16 + (lane & 15);
                int c2  = kc * 2 + (lane >> 4);
                ldsm4(aq[mt], smem_u32(Ac + row * GSTRH + c2 * 8));
            }
#pragma unroll
            for (int ntp = 0; ntp < 2; ntp++) {
                int row = wn * 32 + ntp * 16 + (lane & 7) + ((lane >> 4) << 3);
                int c2  = kc * 2 + ((lane >> 3) & 1);
                ldsm4(bk[ntp], smem_u32(Bc + row * GSTRH + c2 * 8));
            }
#pragma unroll
            for (int mt = 0; mt < 4; mt++)
#pragma unroll
                for (int ntp = 0; ntp < 2; ntp++) {
                    mma_f16(acc[mt][2*ntp],   aq[mt], bk[ntp][0], bk[ntp][1]);
                    mma_f16(acc[mt][2*ntp+1], aq[mt], bk[ntp][2], bk[ntp][3]);
                }
        }
        // no trailing barrier: top-of-loop barrier orders stage reuse
    }

    // epilogue
#pragma unroll
    for (int mt = 0; mt < 4; mt++) {
        int row = m0 + wm * 64 + mt * 16 + gid;
#pragma unroll
        for (int nt = 0; nt < 4; nt++) {
            int col = n0 + wn * 32 + nt * 8 + 2 * tig;
            if (sizeof(OutT) == 4) {
                *(float2*)&((float*)C)[(long)row * N + col] =
                    make_float2(acc[mt][nt][0], acc[mt][nt][1]);
                *(float2*)&((float*)C)[(long)(row + 8) * N + col] =
                    make_float2(acc[mt][nt][2], acc[mt][nt][3]);
            } else {
                *(__half2*)&((__half*)C)[(long)row * N + col] =
                    __floats2half2_rn(acc[mt][nt][0], acc[mt][nt][1]);
                *(__half2*)&((__half*)C)[(long)(row + 8) * N + col] =
                    __floats2half2_rn(acc[mt][nt][2], acc[mt][nt][3]);
            }
        }
    }
}

// =====================================================================
// Fused per-head RMSNorm + RoPE from fp16 qkv into head-major bufs.
// grid = (T, 40): 0..31 q heads (scaled by 1/sqrt(D)*log2e), 32..39 k.
// =====================================================================
__global__ void rmsnorm_rope_kernel(
    const __half* __restrict__ qkv, const int* __restrict__ positions,
    const float* __restrict__ qw, const float* __restrict__ kw,
    __half* __restrict__ q16, __half* __restrict__ k16)
{
    int t  = blockIdx.x;
    int hh = blockIdx.y;
    int d  = threadIdx.x;          // 0..127

    bool isq = (hh < NHEADS);
    int off = isq ? hh * HDIM : QSIZE + (hh - NHEADS) * HDIM;
    const float* w = isq ? qw : kw;
    const __half* x = qkv + (long)t * QKVW + off;
    __half* outp = isq ? (q16 + ((long)hh * T + t) * HDIM)
                       : (k16 + ((long)(hh - NHEADS) * T + t) * HDIM);
    float oscale = isq ? SCALING * LOG2E : 1.0f;

    float v = __half2float(x[d]);
    float ss = v * v;
#pragma unroll
    for (int o = 16; o >= 1; o >>= 1)
        ss += __shfl_xor_sync(0xffffffffu, ss, o);

    __shared__ float sred[4];
    __shared__ float snorm;
    __shared__ float sx[HDIM];
    int lane = d & 31, wp = d >> 5;
    if (lane == 0) sred[wp] = ss;
    __syncthreads();
    if (d == 0) {
        float tot = sred[0] + sred[1] + sred[2] + sred[3];
        snorm = rsqrtf(tot / (float)HDIM + 1e-6f);
    }
    __syncthreads();

    float nv = v * snorm * w[d];
    sx[d] = nv;
    __syncthreads();

    if (d < 64) {
        float x1 = sx[d];
        float x2 = sx[d + 64];
        float pos = (float)positions[t];
        float invf = powf(10000.0f, -((float)d) / 64.0f);
        float ang = pos * invf;
        float c, s;
        sincosf(ang, &s, &c);
        outp[d]      = __float2half_rn((x1 * c - x2 * s) * oscale);
        outp[d + 64] = __float2half_rn((x2 * c + x1 * s) * oscale);
    }
}

// =====================================================================
// fp16 flash attention (causal, GQA). Output fp16.
// Q pre-scaled by 1/sqrt(D)*log2e -> softmax via exp2f.
// V read directly from fp16 qkv (row stride QKVW).
// Largest q-tiles scheduled first (qb reversed).
// =====================================================================
#define FSTR 136
#define FQ_H (128 * FSTR)
#define FKV_H (64 * FSTR)
#define FLASH_SMEM ((FQ_H + 4 * FKV_H) * 2)   // 104448 B

__global__ __launch_bounds__(256, 2) void flash_h16(
    const __half* __restrict__ Q, const __half* __restrict__ Kh,
    const __half* __restrict__ qkv16, __half* __restrict__ O)
{
    int qb = gridDim.x - 1 - blockIdx.x;   // big tiles first
    int h  = blockIdx.y;
    int kvh = h >> 2;
    int q0 = qb * 128;

    extern __shared__ __half smf[];
    __half* Qs = smf;                 // [128][136]
    __half* Ks = smf + FQ_H;          // [2][64][136]
    __half* Vs = Ks + 2 * FKV_H;      // [2][64][136]

    int tid = threadIdx.x;
    int lane = tid & 31, warp = tid >> 5;
    int gid = lane >> 2, tig = lane & 3;

    const __half* Qg = Q + ((long)h * T + q0) * HDIM;
    const __half* Kg = Kh + (long)kvh * T * HDIM;
    const __half* Vg = qkv16 + QSIZE + KVSIZE + kvh * HDIM;   // + t*QKVW

#pragma unroll
    for (int i = 0; i < 8; i++) {
        int idx = tid + i * 256;
        int r = idx >> 4, c = idx & 15;
        cp16(smem_u32(Qs + r * FSTR + c * 8), Qg + r * HDIM + c * 8);
    }
#pragma unroll
    for (int i = 0; i < 4; i++) {
        int idx = tid + i * 256;
        int r = idx >> 4, c = idx & 15;
        cp16(smem_u32(Ks + r * FSTR + c * 8), Kg + (long)r * HDIM + c * 8);
        cp16(smem_u32(Vs + r * FSTR + c * 8), Vg + (long)r * QKVW + c * 8);
    }
    cp_commit();

    float m0s = -1e30f, m1s = -1e30f, l0s = 0.f, l1s = 0.f;
    float oacc[16][4];
#pragma unroll
    for (int nt = 0; nt < 16; nt++)
#pragma unroll
        for (int r = 0; r < 4; r++) oacc[nt][r] = 0.f;

    int r0 = q0 + warp * 16 + gid;
    int r1 = r0 + 8;
    int kbmax = 2 * qb + 1;

    for (int kb = 0; kb <= kbmax; kb++) {
        cp_wait<0>();
        __syncthreads();

        if (kb < kbmax) {
            __half* Kn = Ks + ((kb + 1) & 1) * FKV_H;
            __half* Vn = Vs + ((kb + 1) & 1) * FKV_H;
            long rowoff = (long)(kb + 1) * 64;
#pragma unroll
            for (int i = 0; i < 4; i++) {
                int idx = tid + i * 256;
                int r = idx >> 4, c = idx & 15;
                cp16(smem_u32(Kn + r * FSTR + c * 8), Kg + (rowoff + r) * HDIM + c * 8);
                cp16(smem_u32(Vn + r * FSTR + c * 8), Vg + (rowoff + r) * QKVW + c * 8);
            }
        }
        cp_commit();

        const __half* Kc = Ks + (kb & 1) * FKV_H;
        const __half* Vc = Vs + (kb & 1) * FKV_H;

        float sacc[8][4];
#pragma unroll
        for (int nt = 0; nt < 8; nt++)
#pragma unroll
            for (int r = 0; r < 4; r++) sacc[nt][r] = 0.f;

#pragma unroll
        for (int kc = 0; kc < 8; kc++) {
            unsigned aq[4];
            {
                int row = warp * 16 + (lane & 15);
                int c2  = kc * 2 + (lane >> 4);
                ldsm4(aq, smem_u32(Qs + row * FSTR + c2 * 8));
            }
#pragma unroll
            for (int ntp = 0; ntp < 4; ntp++) {
                unsigned bk[4];
                int row = ntp * 16 + (lane & 7) + ((lane >> 4) << 3);
                int c2  = kc * 2 + ((lane >> 3) & 1);
                ldsm4(bk, smem_u32(Kc + row * FSTR + c2 * 8));
                mma_f16(sacc[2*ntp],   aq, bk[0], bk[1]);
                mma_f16(sacc[2*ntp+1], aq, bk[2], bk[3]);
            }
        }

        if (kb >= 2 * qb) {
#pragma unroll
            for (int nt = 0; nt < 8; nt++) {
                int colb = kb * 64 + nt * 8 + 2 * tig;
                if (colb > r0)     sacc[nt][0] = -1e30f;
                if (colb + 1 > r0) sacc[nt][1] = -1e30f;
                if (colb > r1)     sacc[nt][2] = -1e30f;
                if (colb + 1 > r1) sacc[nt][3] = -1e30f;
            }
        }

        float mx0 = -1e30f, mx1 = -1e30f;
#pragma unroll
        for (int nt = 0; nt < 8; nt++) {
            mx0 = fmaxf(mx0, fmaxf(sacc[nt][0], sacc[nt][1]));
            mx1 = fmaxf(mx1, fmaxf(sacc[nt][2], sacc[nt][3]));
        }
        mx0 = fmaxf(mx0, __shfl_xor_sync(0xffffffffu, mx0, 1));
        mx0 = fmaxf(mx0, __shfl_xor_sync(0xffffffffu, mx0, 2));
        mx1 = fmaxf(mx1, __shfl_xor_sync(0xffffffffu, mx1, 1));
        mx1 = fmaxf(mx1, __shfl_xor_sync(0xffffffffu, mx1, 2));

        float mn0 = fmaxf(m0s, mx0);
        float mn1 = fmaxf(m1s, mx1);
        float corr0 = exp2f(m0s - mn0);
        float corr1 = exp2f(m1s - mn1);

        float ls0 = 0.f, ls1 = 0.f;
#pragma unroll
        for (int nt = 0; nt < 8; nt++) {
            sacc[nt][0] = exp2f(sacc[nt][0] - mn0);
            sacc[nt][1] = exp2f(sacc[nt][1] - mn0);
            sacc[nt][2] = exp2f(sacc[nt][2] - mn1);
            sacc[nt][3] = exp2f(sacc[nt][3] - mn1);
            ls0 += sacc[nt][0] + sacc[nt][1];
            ls1 += sacc[nt][2] + sacc[nt][3];
        }
        ls0 += __shfl_xor_sync(0xffffffffu, ls0, 1);
        ls0 += __shfl_xor_sync(0xffffffffu, ls0, 2);
        ls1 += __shfl_xor_sync(0xffffffffu, ls1, 1);
        ls1 += __shfl_xor_sync(0xffffffffu, ls1, 2);

        l0s = l0s * corr0 + ls0;
        l1s = l1s * corr1 + ls1;
        m0s = mn0;
        m1s = mn1;

#pragma unroll
        for (int nt = 0; nt < 16; nt++) {
            oacc[nt][0] *= corr0;
            oacc[nt][1] *= corr0;
            oacc[nt][2] *= corr1;
            oacc[nt][3] *= corr1;
        }

#pragma unroll
        for (int kc2 = 0; kc2 < 4; kc2++) {
            unsigned ap[4];
            ap[0] = pack_h2(sacc[2*kc2][0],   sacc[2*kc2][1]);
            ap[1] = pack_h2(sacc[2*kc2][2],   sacc[2*kc2][3]);
            ap[2] = pack_h2(sacc[2*kc2+1][0], sacc[2*kc2+1][1]);
            ap[3] = pack_h2(sacc[2*kc2+1][2], sacc[2*kc2+1][3]);
#pragma unroll
            for (int ntp = 0; ntp < 8; ntp++) {
                unsigned bv[4];
                int row = kc2 * 16 + (lane & 7) + (((lane >> 3) & 1) << 3);
                int c2  = ntp * 2 + (lane >> 4);
                ldsm4t(bv, smem_u32(Vc + row * FSTR + c2 * 8));
                mma_f16(oacc[2*ntp],   ap, bv[0], bv[1]);
                mma_f16(oacc[2*ntp+1], ap, bv[2], bv[3]);
            }
        }
    }

    float inv0 = 1.0f / l0s;
    float inv1 = 1.0f / l1s;
#pragma unroll
    for (int nt = 0; nt < 16; nt++) {
        int col = h * HDIM + nt * 8 + 2 * tig;
        *(__half2*)&O[(long)r0 * QSIZE + col] =
            __floats2half2_rn(oacc[nt][0] * inv0, oacc[nt][1] * inv0);
        *(__half2*)&O[(long)r1 * QSIZE + col] =
            __floats2half2_rn(oacc[nt][2] * inv1, oacc[nt][3] * inv1);
    }
}

// =====================================================================
// launch
// =====================================================================
extern "C" void kernel_launch(void* const* d_in, const int* in_sizes, int n_in,
                              void* d_out, int out_size)
{
    const int*   positions = (const int*)d_in[0];
    const float* hidden    = (const float*)d_in[1];
    const float* wqkv      = (const float*)d_in[2];
    const float* wo        = (const float*)d_in[3];
    const float* qnw       = (const float*)d_in[4];
    const float* knw       = (const float*)d_in[5];
    float* out = (float*)d_out;

    __half *qkv16, *h16, *wqkv16, *wo16, *q16, *k16, *o16;
    cudaGetSymbolAddress((void**)&qkv16, g_qkv16);
    cudaGetSymbolAddress((void**)&h16, g_h16);
    cudaGetSymbolAddress((void**)&wqkv16, g_wqkv16);
    cudaGetSymbolAddress((void**)&wo16, g_wo16);
    cudaGetSymbolAddress((void**)&q16, g_q16);
    cudaGetSymbolAddress((void**)&k16, g_k16);
    cudaGetSymbolAddress((void**)&o16, g_o16);

    static bool attr_done = false;
    if (!attr_done) {
        cudaFuncSetAttribute(gemm_h16<__half>,
                             cudaFuncAttributeMaxDynamicSharedMemorySize, GEMM_SMEM);
        cudaFuncSetAttribute(gemm_h16<float>,
                             cudaFuncAttributeMaxDynamicSharedMemorySize, GEMM_SMEM);
        cudaFuncSetAttribute(flash_h16,
                             cudaFuncAttributeMaxDynamicSharedMemorySize, FLASH_SMEM);
        attr_done = true;
    }

    // 0) fp32 -> fp16 converts
    f2h_kernel<<<2048, 256>>>(hidden, h16, (long)T * HIDDEN);
    f2h_kernel<<<4096, 256>>>(wqkv, wqkv16, (long)QKVW * HIDDEN);
    f2h_kernel<<<4096, 256>>>(wo, wo16, (long)HIDDEN * QSIZE);

    // 1) qkv16 = hidden @ wqkv^T   [2048, 6144] fp16
    {
        dim3 grid(QKVW / 128, T / 128);
        gemm_h16<__half><<<grid, 256, GEMM_SMEM>>>(h16, wqkv16, qkv16, T, QKVW, HIDDEN);
    }
    // 2) rmsnorm + rope head-major repack (q scaled by 1/sqrt(D)*log2e)
    {
        dim3 grid(T, NHEADS + NKV);
        rmsnorm_rope_kernel<<<grid, 128>>>(qkv16, positions, qnw, knw, q16, k16);
    }
    // 3) causal flash attention -> o16 [2048, 4096] fp16 (V from qkv16)
    {
        dim3 grid(T / 128, NHEADS);
        flash_h16<<<grid, 256, FLASH_SMEM>>>(q16, k16, qkv16, o16);
    }
    // 4) out = o @ wo^T   [2048, 2048] fp32
    {
        dim3 grid(HIDDEN / 128, T / 128);
        gemm_h16<float><<<grid, 256, GEMM_SMEM>>>(o16, wo16, out, T, HIDDEN, QSIZE);
    }
}